// round 1
// baseline (speedup 1.0000x reference)
#include <cuda_runtime.h>
#include <cstddef>

#define NB 8
#define NT 8192
#define ND 128
#define NS 128
#define CK 64
#define NC (NT / CK)   // 128

// Scratch (allocation-free rule: __device__ globals)
__device__ float g_hl[(size_t)NB * NT * NS];   // p_t * local cumsum (h_local)
__device__ float g_p [(size_t)NB * NT * NS];   // p_t = exp(clip(cumsum la, -30, 0))
__device__ float g_C [(size_t)NB * NT * NS];   // C projection
__device__ float g_h0[(size_t)NB * NC * NS];   // chunk-entry state after inter-chunk scan

// ---------------------------------------------------------------------------
// Pass 1: per-chunk projections + in-register clipped scan.
// grid = (NC, NB), block = 128 (thread == state s)
// smem = 3 transposed W (pad 129) + x chunk
// ---------------------------------------------------------------------------
#define SMEM1_FLOATS (3 * 128 * 129 + 64 * 128)

__global__ __launch_bounds__(128, 1)
void pass1_kernel(const float* __restrict__ x,
                  const float* __restrict__ log_A,
                  const float* __restrict__ W_B,
                  const float* __restrict__ W_C,
                  const float* __restrict__ W_dt,
                  const float* __restrict__ b_dt)
{
    extern __shared__ float sm[];
    float* sWdt = sm;
    float* sWb  = sWdt + 128 * 129;
    float* sWc  = sWb  + 128 * 129;
    float* sx   = sWc  + 128 * 129;   // 64 x 128

    const int c = blockIdx.x, b = blockIdx.y, tid = threadIdx.x;

    // Load W transposed: sW[k*129 + s] = W[s*128 + k]  (conflict-free: 129 = 1 mod 32)
    for (int i = tid; i < 128 * 128; i += 128) {
        int s = i >> 7, k = i & 127;
        sWdt[k * 129 + s] = W_dt[i];
        sWb [k * 129 + s] = W_B[i];
        sWc [k * 129 + s] = W_C[i];
    }
    const float4* xg = (const float4*)(x + ((size_t)b * NT + (size_t)c * CK) * ND);
    float4* sx4 = (float4*)sx;
    for (int i = tid; i < 64 * 32; i += 128) sx4[i] = xg[i];
    __syncthreads();

    const int s = tid;
    const float A_s = -fminf(expf(log_A[s]), 10.0f);
    const float bd  = b_dt[s];

    float cs = 0.0f;    // raw cumsum of la within chunk
    float acc = 0.0f;   // cumsum of u * exp(-log_p)
    const size_t gb = ((size_t)b * NT + (size_t)c * CK) * NS + s;

    for (int tt = 0; tt < 8; ++tt) {
        float adt[8], ab[8], ac[8];
#pragma unroll
        for (int i = 0; i < 8; ++i) { adt[i] = 0.f; ab[i] = 0.f; ac[i] = 0.f; }

#pragma unroll 4
        for (int k = 0; k < 128; k += 4) {
            float wd0 = sWdt[(k + 0) * 129 + s];
            float wd1 = sWdt[(k + 1) * 129 + s];
            float wd2 = sWdt[(k + 2) * 129 + s];
            float wd3 = sWdt[(k + 3) * 129 + s];
            float wb0 = sWb[(k + 0) * 129 + s];
            float wb1 = sWb[(k + 1) * 129 + s];
            float wb2 = sWb[(k + 2) * 129 + s];
            float wb3 = sWb[(k + 3) * 129 + s];
            float wc0 = sWc[(k + 0) * 129 + s];
            float wc1 = sWc[(k + 1) * 129 + s];
            float wc2 = sWc[(k + 2) * 129 + s];
            float wc3 = sWc[(k + 3) * 129 + s];
#pragma unroll
            for (int i = 0; i < 8; ++i) {
                float4 xv = *(const float4*)&sx[(tt * 8 + i) * 128 + k];
                adt[i] = fmaf(xv.x, wd0, fmaf(xv.y, wd1, fmaf(xv.z, wd2, fmaf(xv.w, wd3, adt[i]))));
                ab[i]  = fmaf(xv.x, wb0, fmaf(xv.y, wb1, fmaf(xv.z, wb2, fmaf(xv.w, wb3, ab[i]))));
                ac[i]  = fmaf(xv.x, wc0, fmaf(xv.y, wc1, fmaf(xv.z, wc2, fmaf(xv.w, wc3, ac[i]))));
            }
        }

        // Sequential (in-token-order) clipped scan for state s
#pragma unroll
        for (int i = 0; i < 8; ++i) {
            const int t = tt * 8 + i;
            float v  = adt[i] + bd;
            float sp = (v > 15.0f) ? v : log1pf(__expf(v));
            float dt = fminf(sp, 1.0f);
            float la = fminf(fmaxf(dt * A_s, -0.5f), 0.0f);
            float u  = ab[i] * dt;
            cs += la;
            float lp = fminf(fmaxf(cs, -30.0f), 0.0f);
            float p  = __expf(lp);
            acc = fmaf(u, __expf(-lp), acc);
            const size_t gi = gb + (size_t)t * NS;
            g_C[gi]  = ac[i];
            g_p[gi]  = p;
            g_hl[gi] = p * acc;
        }
    }
}

// ---------------------------------------------------------------------------
// Pass 2: inter-chunk prefix scan of chunk-tail states.
// grid = NB, block = 128 (thread == state s)
// ---------------------------------------------------------------------------
#define SMEM2_FLOATS (2 * 128 * 128)

__global__ __launch_bounds__(128)
void pass2_kernel()
{
    extern __shared__ float sm[];
    float* sP = sm;              // [c][s]
    float* sH = sm + 128 * 128;  // [c][s]
    const int b = blockIdx.x, tid = threadIdx.x;

    const size_t bb = (size_t)b * NT * NS;
    for (int i = tid; i < 128 * 128; i += 128) {
        int c = i >> 7, s = i & 127;
        size_t gi = bb + (size_t)(c * CK + (CK - 1)) * NS + s;
        sP[i] = g_p[gi];
        sH[i] = g_hl[gi];
    }
    __syncthreads();

    const int s = tid;
    float h0 = 0.0f;
    const size_t hb = (size_t)b * NC * NS + s;
#pragma unroll 8
    for (int c = 0; c < NC; ++c) {
        g_h0[hb + (size_t)c * NS] = h0;
        h0 = fmaf(sP[c * 128 + s], h0, sH[c * 128 + s]);
    }
}

// ---------------------------------------------------------------------------
// Pass 3: h = hl + p*h0; y = sum_s C*h; out = h @ W_out^T + y * x[...,0]
// grid = (NC, NB), block = 128 (thread == output dim d)
// ---------------------------------------------------------------------------
#define SMEM3_FLOATS (128 * 129 + 64 * 132 + 64 + 128 + 64)

__global__ __launch_bounds__(128)
void pass3_kernel(const float* __restrict__ x,
                  const float* __restrict__ W_out,
                  float* __restrict__ out)
{
    extern __shared__ float sm[];
    float* sWo = sm;                 // [s*129 + d]
    float* sh  = sWo + 128 * 129;    // [t*132 + s]
    float* sy  = sh  + 64 * 132;     // [t]
    float* sh0 = sy  + 64;           // [s]
    float* sx0 = sh0 + 128;          // [t]

    const int c = blockIdx.x, b = blockIdx.y, tid = threadIdx.x;
    const size_t tbase = (size_t)b * NT + (size_t)c * CK;
    const size_t gbase = tbase * NS;

    // W_out transposed into smem: sWo[s*129+d] = W_out[d*128+s]
    for (int i = tid; i < 128 * 128; i += 128) {
        int d = i >> 7, s = i & 127;
        sWo[s * 129 + d] = W_out[i];
    }
    sh0[tid] = g_h0[((size_t)b * NC + c) * NS + tid];
    if (tid < 64) sx0[tid] = x[(tbase + tid) * ND];
    __syncthreads();

    // Reconstruct h into smem
    for (int i = tid; i < 64 * 128; i += 128) {
        int t = i >> 7, s = i & 127;
        sh[t * 132 + s] = fmaf(g_p[gbase + i], sh0[s], g_hl[gbase + i]);
    }
    __syncthreads();

    // y[t] = sum_s C[t][s] * h[t][s]  (warp w -> tokens w*16..w*16+15)
    {
        const int w = tid >> 5, l = tid & 31;
        const float4* C4 = (const float4*)(g_C + gbase);
        for (int t = w * 16; t < w * 16 + 16; ++t) {
            float4 cv = C4[t * 32 + l];
            const float* hr = &sh[t * 132 + l * 4];
            float v = cv.x * hr[0] + cv.y * hr[1] + cv.z * hr[2] + cv.w * hr[3];
#pragma unroll
            for (int o = 16; o; o >>= 1) v += __shfl_xor_sync(0xFFFFFFFFu, v, o);
            if (l == 0) sy[t] = v;
        }
    }
    __syncthreads();

    // out GEMM
    const int d = tid;
    float* outp = out + gbase + d;
    for (int tt = 0; tt < 8; ++tt) {
        float accv[8];
#pragma unroll
        for (int i = 0; i < 8; ++i) accv[i] = 0.f;
#pragma unroll 4
        for (int s = 0; s < 128; s += 4) {
            float w0 = sWo[(s + 0) * 129 + d];
            float w1 = sWo[(s + 1) * 129 + d];
            float w2 = sWo[(s + 2) * 129 + d];
            float w3 = sWo[(s + 3) * 129 + d];
#pragma unroll
            for (int i = 0; i < 8; ++i) {
                const float4 hv = *(const float4*)&sh[(tt * 8 + i) * 132 + s];
                accv[i] = fmaf(hv.x, w0, fmaf(hv.y, w1, fmaf(hv.z, w2, fmaf(hv.w, w3, accv[i]))));
            }
        }
#pragma unroll
        for (int i = 0; i < 8; ++i) {
            const int t = tt * 8 + i;
            outp[(size_t)t * NS] = accv[i] + sy[t] * sx0[t];
        }
    }
}

// ---------------------------------------------------------------------------
extern "C" void kernel_launch(void* const* d_in, const int* in_sizes, int n_in,
                              void* d_out, int out_size)
{
    const float* x     = (const float*)d_in[0];
    const float* log_A = (const float*)d_in[1];
    const float* W_B   = (const float*)d_in[2];
    const float* W_C   = (const float*)d_in[3];
    const float* W_dt  = (const float*)d_in[4];
    const float* b_dt  = (const float*)d_in[5];
    const float* W_out = (const float*)d_in[6];
    float* out = (float*)d_out;

    const int smem1 = SMEM1_FLOATS * 4;   // 230912
    const int smem2 = SMEM2_FLOATS * 4;   // 131072
    const int smem3 = SMEM3_FLOATS * 4;   // 100864
    cudaFuncSetAttribute(pass1_kernel, cudaFuncAttributeMaxDynamicSharedMemorySize, smem1);
    cudaFuncSetAttribute(pass2_kernel, cudaFuncAttributeMaxDynamicSharedMemorySize, smem2);
    cudaFuncSetAttribute(pass3_kernel, cudaFuncAttributeMaxDynamicSharedMemorySize, smem3);

    pass1_kernel<<<dim3(NC, NB), 128, smem1>>>(x, log_A, W_B, W_C, W_dt, b_dt);
    pass2_kernel<<<NB, 128, smem2>>>();
    pass3_kernel<<<dim3(NC, NB), 128, smem3>>>(x, W_out, out);
}

// round 2
// speedup vs baseline: 1.3762x; 1.3762x over previous
#include <cuda_runtime.h>
#include <cstddef>

#define NB 8
#define NT 8192
#define ND 128
#define NS 128
#define CK 64
#define NC (NT / CK)   // 128

// Scratch (allocation-free rule: __device__ globals)
__device__ float g_hl[(size_t)NB * NT * NS];   // p_t * local cumsum (h_local)
__device__ float g_p [(size_t)NB * NT * NS];   // p_t = exp(clip(cumsum la, -30, 0))
__device__ float g_C [(size_t)NB * NT * NS];   // C projection
__device__ float g_h0[(size_t)NB * NC * NS];   // chunk-entry state after inter-chunk scan

// ---------------------------------------------------------------------------
// Pass 1: 2 chunks per block, 256 threads (warps 0-3 -> chunk0, 4-7 -> chunk1).
// W (3x 128x129 padded transpose) shared by both chunks; x staged per 8-token
// tile (2x 4KB) so total smem ~206KB, giving 8 warps/SM instead of 4.
// ---------------------------------------------------------------------------
#define SMEM1_FLOATS (3 * 128 * 129 + 2 * 8 * 128)

__global__ __launch_bounds__(256, 1)
void pass1_kernel(const float* __restrict__ x,
                  const float* __restrict__ log_A,
                  const float* __restrict__ W_B,
                  const float* __restrict__ W_C,
                  const float* __restrict__ W_dt,
                  const float* __restrict__ b_dt)
{
    extern __shared__ float sm[];
    float* sWdt = sm;
    float* sWb  = sWdt + 128 * 129;
    float* sWc  = sWb  + 128 * 129;
    float* sx   = sWc  + 128 * 129;   // [2][8*128]

    const int b = blockIdx.y, tid = threadIdx.x;
    const int ch = tid >> 7;              // which chunk half this thread serves
    const int s  = tid & 127;
    const int c  = blockIdx.x * 2 + ch;   // global chunk id

    // Load W transposed: sW[k*129 + s] = W[s*128 + k] (conflict-free both ways)
    for (int i = tid; i < 128 * 128; i += 256) {
        int ss = i >> 7, k = i & 127;
        sWdt[k * 129 + ss] = W_dt[i];
        sWb [k * 129 + ss] = W_B[i];
        sWc [k * 129 + ss] = W_C[i];
    }

    const float A_s = -fminf(expf(log_A[s]), 10.0f);
    const float bd  = b_dt[s];

    float cs = 0.0f;    // raw cumsum of la within chunk
    float acc = 0.0f;   // cumsum of u * exp(-log_p)
    const size_t gb = ((size_t)b * NT + (size_t)c * CK) * NS + s;

    const float4* xg0 = (const float4*)(x + ((size_t)b * NT + (size_t)(blockIdx.x * 2) * CK) * ND);
    const float4* xg1 = (const float4*)(x + ((size_t)b * NT + (size_t)(blockIdx.x * 2 + 1) * CK) * ND);
    float4* sx4 = (float4*)sx;
    const float* mysx = sx + ch * (8 * 128);

    for (int tt = 0; tt < 8; ++tt) {
        __syncthreads();   // previous tile fully consumed
        // stage 8-token x tiles for both chunks: 512 float4, 2 per thread
#pragma unroll
        for (int r = 0; r < 2; ++r) {
            int f = tid + r * 256;             // [0,512)
            int chl = f >> 8, w = f & 255;     // w = token*32 + k4
            const float4* src = chl ? xg1 : xg0;
            sx4[chl * 256 + w] = src[tt * 256 + w];
        }
        __syncthreads();

        float adt[8], ab[8], ac[8];
#pragma unroll
        for (int i = 0; i < 8; ++i) { adt[i] = 0.f; ab[i] = 0.f; ac[i] = 0.f; }

#pragma unroll 4
        for (int k = 0; k < 128; k += 4) {
            float wd0 = sWdt[(k + 0) * 129 + s];
            float wd1 = sWdt[(k + 1) * 129 + s];
            float wd2 = sWdt[(k + 2) * 129 + s];
            float wd3 = sWdt[(k + 3) * 129 + s];
            float wb0 = sWb[(k + 0) * 129 + s];
            float wb1 = sWb[(k + 1) * 129 + s];
            float wb2 = sWb[(k + 2) * 129 + s];
            float wb3 = sWb[(k + 3) * 129 + s];
            float wc0 = sWc[(k + 0) * 129 + s];
            float wc1 = sWc[(k + 1) * 129 + s];
            float wc2 = sWc[(k + 2) * 129 + s];
            float wc3 = sWc[(k + 3) * 129 + s];
#pragma unroll
            for (int i = 0; i < 8; ++i) {
                float4 xv = *(const float4*)&mysx[i * 128 + k];
                adt[i] = fmaf(xv.x, wd0, fmaf(xv.y, wd1, fmaf(xv.z, wd2, fmaf(xv.w, wd3, adt[i]))));
                ab[i]  = fmaf(xv.x, wb0, fmaf(xv.y, wb1, fmaf(xv.z, wb2, fmaf(xv.w, wb3, ab[i]))));
                ac[i]  = fmaf(xv.x, wc0, fmaf(xv.y, wc1, fmaf(xv.z, wc2, fmaf(xv.w, wc3, ac[i]))));
            }
        }

        // Sequential (token-order) clipped scan for state s
#pragma unroll
        for (int i = 0; i < 8; ++i) {
            const int t = tt * 8 + i;
            float v  = adt[i] + bd;
            float sp = (v > 15.0f) ? v : __logf(1.0f + __expf(v));
            float dt = fminf(sp, 1.0f);
            float la = fminf(fmaxf(dt * A_s, -0.5f), 0.0f);
            float u  = ab[i] * dt;
            cs += la;
            float lp = fminf(fmaxf(cs, -30.0f), 0.0f);
            float p  = __expf(lp);
            acc = fmaf(u, __expf(-lp), acc);
            const size_t gi = gb + (size_t)t * NS;
            g_C[gi]  = ac[i];
            g_p[gi]  = p;
            g_hl[gi] = p * acc;
        }
    }
}

// ---------------------------------------------------------------------------
// Pass 2: inter-chunk prefix scan of chunk-tail states.
// grid = NB, block = 128 (thread == state s)
// ---------------------------------------------------------------------------
#define SMEM2_FLOATS (2 * 128 * 128)

__global__ __launch_bounds__(128)
void pass2_kernel()
{
    extern __shared__ float sm[];
    float* sP = sm;              // [c][s]
    float* sH = sm + 128 * 128;  // [c][s]
    const int b = blockIdx.x, tid = threadIdx.x;

    const size_t bb = (size_t)b * NT * NS;
    for (int i = tid; i < 128 * 128; i += 128) {
        int c = i >> 7, s = i & 127;
        size_t gi = bb + (size_t)(c * CK + (CK - 1)) * NS + s;
        sP[i] = g_p[gi];
        sH[i] = g_hl[gi];
    }
    __syncthreads();

    const int s = tid;
    float h0 = 0.0f;
    const size_t hb = (size_t)b * NC * NS + s;
#pragma unroll 8
    for (int c = 0; c < NC; ++c) {
        g_h0[hb + (size_t)c * NS] = h0;
        h0 = fmaf(sP[c * 128 + s], h0, sH[c * 128 + s]);
    }
}

// ---------------------------------------------------------------------------
// Pass 3: h = hl + p*h0; y = sum_s C*h; out = h @ W_out^T + y * x[...,0]
// grid = (NC, NB), block = 256: thread (d = tid&127, token-half = tid>>7).
// smem ~100KB -> 2 blocks/SM = 16 warps/SM.
// ---------------------------------------------------------------------------
#define SMEM3_FLOATS (128 * 129 + 64 * 132 + 64 + 128 + 64)

__global__ __launch_bounds__(256)
void pass3_kernel(const float* __restrict__ x,
                  const float* __restrict__ W_out,
                  float* __restrict__ out)
{
    extern __shared__ float sm[];
    float* sWo = sm;                 // [s*129 + d]
    float* sh  = sWo + 128 * 129;    // [t*132 + s]
    float* sy  = sh  + 64 * 132;     // [t]
    float* sh0 = sy  + 64;           // [s]
    float* sx0 = sh0 + 128;          // [t]

    const int c = blockIdx.x, b = blockIdx.y, tid = threadIdx.x;
    const size_t tbase = (size_t)b * NT + (size_t)c * CK;
    const size_t gbase = tbase * NS;

    // W_out transposed into smem: sWo[s*129+d] = W_out[d*128+s]
    for (int i = tid; i < 128 * 128; i += 256) {
        int d = i >> 7, s = i & 127;
        sWo[s * 129 + d] = W_out[i];
    }
    if (tid < 128) sh0[tid] = g_h0[((size_t)b * NC + c) * NS + tid];
    else if (tid < 192) sx0[tid - 128] = x[(tbase + tid - 128) * ND];
    __syncthreads();

    // Reconstruct h into smem
    for (int i = tid; i < 64 * 128; i += 256) {
        int t = i >> 7, s = i & 127;
        sh[t * 132 + s] = fmaf(g_p[gbase + i], sh0[s], g_hl[gbase + i]);
    }
    __syncthreads();

    // y[t] = sum_s C[t][s] * h[t][s]  (8 warps -> 8 tokens each)
    {
        const int w = tid >> 5, l = tid & 31;
        const float4* C4 = (const float4*)(g_C + gbase);
        for (int t = w * 8; t < w * 8 + 8; ++t) {
            float4 cv = C4[t * 32 + l];
            const float* hr = &sh[t * 132 + l * 4];
            float v = cv.x * hr[0] + cv.y * hr[1] + cv.z * hr[2] + cv.w * hr[3];
#pragma unroll
            for (int o = 16; o; o >>= 1) v += __shfl_xor_sync(0xFFFFFFFFu, v, o);
            if (l == 0) sy[t] = v;
        }
    }
    __syncthreads();

    // out GEMM: thread (d, token-half); each thread does 32 tokens
    const int d = tid & 127;
    const int th = tid >> 7;
    float* outp = out + gbase + d;
    for (int tt = th * 4; tt < th * 4 + 4; ++tt) {
        float accv[8];
#pragma unroll
        for (int i = 0; i < 8; ++i) accv[i] = 0.f;
#pragma unroll 4
        for (int s = 0; s < 128; s += 4) {
            float w0 = sWo[(s + 0) * 129 + d];
            float w1 = sWo[(s + 1) * 129 + d];
            float w2 = sWo[(s + 2) * 129 + d];
            float w3 = sWo[(s + 3) * 129 + d];
#pragma unroll
            for (int i = 0; i < 8; ++i) {
                const float4 hv = *(const float4*)&sh[(tt * 8 + i) * 132 + s];
                accv[i] = fmaf(hv.x, w0, fmaf(hv.y, w1, fmaf(hv.z, w2, fmaf(hv.w, w3, accv[i]))));
            }
        }
#pragma unroll
        for (int i = 0; i < 8; ++i) {
            const int t = tt * 8 + i;
            outp[(size_t)t * NS] = accv[i] + sy[t] * sx0[t];
        }
    }
}

// ---------------------------------------------------------------------------
extern "C" void kernel_launch(void* const* d_in, const int* in_sizes, int n_in,
                              void* d_out, int out_size)
{
    const float* x     = (const float*)d_in[0];
    const float* log_A = (const float*)d_in[1];
    const float* W_B   = (const float*)d_in[2];
    const float* W_C   = (const float*)d_in[3];
    const float* W_dt  = (const float*)d_in[4];
    const float* b_dt  = (const float*)d_in[5];
    const float* W_out = (const float*)d_in[6];
    float* out = (float*)d_out;

    const int smem1 = SMEM1_FLOATS * 4;   // 206336
    const int smem2 = SMEM2_FLOATS * 4;   // 131072
    const int smem3 = SMEM3_FLOATS * 4;   // 100864
    cudaFuncSetAttribute(pass1_kernel, cudaFuncAttributeMaxDynamicSharedMemorySize, smem1);
    cudaFuncSetAttribute(pass2_kernel, cudaFuncAttributeMaxDynamicSharedMemorySize, smem2);
    cudaFuncSetAttribute(pass3_kernel, cudaFuncAttributeMaxDynamicSharedMemorySize, smem3);

    pass1_kernel<<<dim3(NC / 2, NB), 256, smem1>>>(x, log_A, W_B, W_C, W_dt, b_dt);
    pass2_kernel<<<NB, 128, smem2>>>();
    pass3_kernel<<<dim3(NC, NB), 256, smem3>>>(x, W_out, out);
}

// round 3
// speedup vs baseline: 1.5378x; 1.1174x over previous
#include <cuda_runtime.h>
#include <cstddef>

#define NB 8
#define NT 8192
#define ND 128
#define NS 128
#define CK 64
#define NC (NT / CK)   // 128

// Scratch (allocation-free rule: __device__ globals)
__device__ float g_hl[(size_t)NB * NT * NS];   // p_t * local cumsum (h_local)
__device__ float g_p [(size_t)NB * NT * NS];   // p_t = exp(clip(cumsum la, -30, 0))
__device__ float g_C [(size_t)NB * NT * NS];   // C projection
__device__ float g_h0[(size_t)NB * NC * NS];   // chunk-entry state after inter-chunk scan

// Packed fp32x2 FMA: acc = a*b + acc (lane-wise), one issue slot for 2 FMAs.
__device__ __forceinline__ void ffma2(unsigned long long& acc,
                                      unsigned long long a,
                                      unsigned long long b)
{
    asm("fma.rn.f32x2 %0, %1, %2, %0;" : "+l"(acc) : "l"(a), "l"(b));
}
__device__ __forceinline__ float hsum2(unsigned long long a)
{
    float2 f = *reinterpret_cast<float2*>(&a);
    return f.x + f.y;
}

// ---------------------------------------------------------------------------
// Pass 1: 2 chunks per 256-thread block (warps 0-3 chunk0, 4-7 chunk1).
// W stored as k-pair float2 transposed rows: sW2[kp*129 + s] = (W[s][2kp], W[s][2kp+1]).
// All 3 projections accumulated with packed FFMA2.
// ---------------------------------------------------------------------------
#define SMEM1_BYTES (3 * 64 * 129 * 8 + 2 * 8 * 128 * 4)   // 206336

__global__ __launch_bounds__(256, 1)
void pass1_kernel(const float* __restrict__ x,
                  const float* __restrict__ log_A,
                  const float* __restrict__ W_B,
                  const float* __restrict__ W_C,
                  const float* __restrict__ W_dt,
                  const float* __restrict__ b_dt)
{
    extern __shared__ float sm[];
    unsigned long long* sWd2 = (unsigned long long*)sm;               // [64*129]
    unsigned long long* sWb2 = sWd2 + 64 * 129;
    unsigned long long* sWc2 = sWb2 + 64 * 129;
    float* sx = (float*)(sWc2 + 64 * 129);                            // [2][8*128]

    const int b = blockIdx.y, tid = threadIdx.x;
    const int ch = tid >> 7;
    const int s  = tid & 127;
    const int c  = blockIdx.x * 2 + ch;

    // Transposed pair layout: sW2[kp*129 + s] = W[s*128 + 2kp .. 2kp+1]
    {
        const unsigned long long* Wd = (const unsigned long long*)W_dt;
        const unsigned long long* Wb = (const unsigned long long*)W_B;
        const unsigned long long* Wc = (const unsigned long long*)W_C;
        for (int i = tid; i < 128 * 64; i += 256) {
            int ss = i >> 6, kp = i & 63;
            sWd2[kp * 129 + ss] = Wd[i];
            sWb2[kp * 129 + ss] = Wb[i];
            sWc2[kp * 129 + ss] = Wc[i];
        }
    }

    const float A_s = -fminf(expf(log_A[s]), 10.0f);
    const float bd  = b_dt[s];

    float cs = 0.0f, acc = 0.0f;
    const size_t gb = ((size_t)b * NT + (size_t)c * CK) * NS + s;

    const float4* xg0 = (const float4*)(x + ((size_t)b * NT + (size_t)(blockIdx.x * 2) * CK) * ND);
    const float4* xg1 = (const float4*)(x + ((size_t)b * NT + (size_t)(blockIdx.x * 2 + 1) * CK) * ND);
    float4* sx4 = (float4*)sx;
    const float* mysx = sx + ch * (8 * 128);

    for (int tt = 0; tt < 8; ++tt) {
        __syncthreads();
#pragma unroll
        for (int r = 0; r < 2; ++r) {
            int f = tid + r * 256;
            int chl = f >> 8, w = f & 255;
            const float4* src = chl ? xg1 : xg0;
            sx4[chl * 256 + w] = src[tt * 256 + w];
        }
        __syncthreads();

        unsigned long long a2d[8], a2b[8], a2c[8];
#pragma unroll
        for (int i = 0; i < 8; ++i) { a2d[i] = 0ULL; a2b[i] = 0ULL; a2c[i] = 0ULL; }

#pragma unroll 4
        for (int kp = 0; kp < 64; kp += 2) {
            unsigned long long wd0 = sWd2[(kp + 0) * 129 + s];
            unsigned long long wd1 = sWd2[(kp + 1) * 129 + s];
            unsigned long long wb0 = sWb2[(kp + 0) * 129 + s];
            unsigned long long wb1 = sWb2[(kp + 1) * 129 + s];
            unsigned long long wc0 = sWc2[(kp + 0) * 129 + s];
            unsigned long long wc1 = sWc2[(kp + 1) * 129 + s];
#pragma unroll
            for (int i = 0; i < 8; ++i) {
                ulonglong2 xq = *(const ulonglong2*)&mysx[i * 128 + kp * 2];
                ffma2(a2d[i], xq.x, wd0); ffma2(a2d[i], xq.y, wd1);
                ffma2(a2b[i], xq.x, wb0); ffma2(a2b[i], xq.y, wb1);
                ffma2(a2c[i], xq.x, wc0); ffma2(a2c[i], xq.y, wc1);
            }
        }

        // Sequential (token-order) clipped scan for state s
#pragma unroll
        for (int i = 0; i < 8; ++i) {
            const int t = tt * 8 + i;
            float v  = hsum2(a2d[i]) + bd;
            float sp = (v > 15.0f) ? v : __logf(1.0f + __expf(v));
            float dt = fminf(sp, 1.0f);
            float la = fminf(fmaxf(dt * A_s, -0.5f), 0.0f);
            float u  = hsum2(a2b[i]) * dt;
            cs += la;
            float lp = fminf(fmaxf(cs, -30.0f), 0.0f);
            float p  = __expf(lp);
            acc = fmaf(u, __expf(-lp), acc);
            const size_t gi = gb + (size_t)t * NS;
            g_C[gi]  = hsum2(a2c[i]);
            g_p[gi]  = p;
            g_hl[gi] = p * acc;
        }
    }
}

// ---------------------------------------------------------------------------
// Pass 2: inter-chunk prefix scan of chunk-tail states.
// ---------------------------------------------------------------------------
#define SMEM2_BYTES (2 * 128 * 128 * 4)

__global__ __launch_bounds__(128)
void pass2_kernel()
{
    extern __shared__ float sm[];
    float* sP = sm;
    float* sH = sm + 128 * 128;
    const int b = blockIdx.x, tid = threadIdx.x;

    const size_t bb = (size_t)b * NT * NS;
    for (int i = tid; i < 128 * 128; i += 128) {
        int c = i >> 7, s = i & 127;
        size_t gi = bb + (size_t)(c * CK + (CK - 1)) * NS + s;
        sP[i] = g_p[gi];
        sH[i] = g_hl[gi];
    }
    __syncthreads();

    const int s = tid;
    float h0 = 0.0f;
    const size_t hb = (size_t)b * NC * NS + s;
#pragma unroll 8
    for (int c = 0; c < NC; ++c) {
        g_h0[hb + (size_t)c * NS] = h0;
        h0 = fmaf(sP[c * 128 + s], h0, sH[c * 128 + s]);
    }
}

// ---------------------------------------------------------------------------
// Pass 3: h = hl + p*h0; y = sum_s C*h; out = h @ W_out^T + y * x[...,0]
// 256 threads: (d = tid&127, token-half = tid>>7). Packed FFMA2 GEMM.
// ---------------------------------------------------------------------------
#define SMEM3_BYTES (64 * 129 * 8 + 64 * 132 * 4 + (64 + 128 + 64) * 4)

__global__ __launch_bounds__(256)
void pass3_kernel(const float* __restrict__ x,
                  const float* __restrict__ W_out,
                  float* __restrict__ out)
{
    extern __shared__ float sm[];
    unsigned long long* sWo2 = (unsigned long long*)sm;   // [sp*129 + d]
    float* sh  = (float*)(sWo2 + 64 * 129);               // [t*132 + s]
    float* sy  = sh  + 64 * 132;
    float* sh0 = sy  + 64;
    float* sx0 = sh0 + 128;

    const int c = blockIdx.x, b = blockIdx.y, tid = threadIdx.x;
    const size_t tbase = (size_t)b * NT + (size_t)c * CK;
    const size_t gbase = tbase * NS;

    // sWo2[sp*129 + d] = (W_out[d][2sp], W_out[d][2sp+1])
    {
        const unsigned long long* Wo = (const unsigned long long*)W_out;
        for (int i = tid; i < 128 * 64; i += 256) {
            int d = i >> 6, sp = i & 63;
            sWo2[sp * 129 + d] = Wo[i];
        }
    }
    if (tid < 128) sh0[tid] = g_h0[((size_t)b * NC + c) * NS + tid];
    else if (tid < 192) sx0[tid - 128] = x[(tbase + tid - 128) * ND];
    __syncthreads();

    for (int i = tid; i < 64 * 128; i += 256) {
        int t = i >> 7, s = i & 127;
        sh[t * 132 + s] = fmaf(g_p[gbase + i], sh0[s], g_hl[gbase + i]);
    }
    __syncthreads();

    // y[t] = sum_s C[t][s] * h[t][s]  (8 warps -> 8 tokens each)
    {
        const int w = tid >> 5, l = tid & 31;
        const float4* C4 = (const float4*)(g_C + gbase);
        for (int t = w * 8; t < w * 8 + 8; ++t) {
            float4 cv = C4[t * 32 + l];
            const float* hr = &sh[t * 132 + l * 4];
            float v = cv.x * hr[0] + cv.y * hr[1] + cv.z * hr[2] + cv.w * hr[3];
#pragma unroll
            for (int o = 16; o; o >>= 1) v += __shfl_xor_sync(0xFFFFFFFFu, v, o);
            if (l == 0) sy[t] = v;
        }
    }
    __syncthreads();

    // out GEMM with packed FFMA2
    const int d = tid & 127;
    const int th = tid >> 7;
    float* outp = out + gbase + d;
    for (int tt = th * 4; tt < th * 4 + 4; ++tt) {
        unsigned long long acc2[8];
#pragma unroll
        for (int i = 0; i < 8; ++i) acc2[i] = 0ULL;
#pragma unroll 4
        for (int sp = 0; sp < 64; sp += 2) {
            unsigned long long w0 = sWo2[(sp + 0) * 129 + d];
            unsigned long long w1 = sWo2[(sp + 1) * 129 + d];
#pragma unroll
            for (int i = 0; i < 8; ++i) {
                ulonglong2 hq = *(const ulonglong2*)&sh[(tt * 8 + i) * 132 + sp * 2];
                ffma2(acc2[i], hq.x, w0);
                ffma2(acc2[i], hq.y, w1);
            }
        }
#pragma unroll
        for (int i = 0; i < 8; ++i) {
            const int t = tt * 8 + i;
            outp[(size_t)t * NS] = hsum2(acc2[i]) + sy[t] * sx0[t];
        }
    }
}

// ---------------------------------------------------------------------------
extern "C" void kernel_launch(void* const* d_in, const int* in_sizes, int n_in,
                              void* d_out, int out_size)
{
    const float* x     = (const float*)d_in[0];
    const float* log_A = (const float*)d_in[1];
    const float* W_B   = (const float*)d_in[2];
    const float* W_C   = (const float*)d_in[3];
    const float* W_dt  = (const float*)d_in[4];
    const float* b_dt  = (const float*)d_in[5];
    const float* W_out = (const float*)d_in[6];
    float* out = (float*)d_out;

    cudaFuncSetAttribute(pass1_kernel, cudaFuncAttributeMaxDynamicSharedMemorySize, SMEM1_BYTES);
    cudaFuncSetAttribute(pass2_kernel, cudaFuncAttributeMaxDynamicSharedMemorySize, SMEM2_BYTES);
    cudaFuncSetAttribute(pass3_kernel, cudaFuncAttributeMaxDynamicSharedMemorySize, SMEM3_BYTES);

    pass1_kernel<<<dim3(NC / 2, NB), 256, SMEM1_BYTES>>>(x, log_A, W_B, W_C, W_dt, b_dt);
    pass2_kernel<<<NB, 128, SMEM2_BYTES>>>();
    pass3_kernel<<<dim3(NC, NB), 256, SMEM3_BYTES>>>(x, W_out, out);
}

// round 4
// speedup vs baseline: 1.6387x; 1.0657x over previous
#include <cuda_runtime.h>
#include <cstddef>

#define NB 8
#define NT 8192
#define ND 128
#define NS 128
#define CK 64
#define NC (NT / CK)   // 128

// Scratch (allocation-free rule: __device__ globals)
__device__ float g_hl[(size_t)NB * NT * NS];   // p_t * local cumsum (h_local)
__device__ float g_p [(size_t)NB * NT * NS];   // p_t = exp(clip(cumsum la, -30, 0))
__device__ float g_C [(size_t)NB * NT * NS];   // C projection
__device__ float g_h0[(size_t)NB * NC * NS];   // chunk-entry state after inter-chunk scan

// Packed fp32x2 FMA: acc = a*b + acc (lane-wise), one issue slot for 2 FMAs.
__device__ __forceinline__ void ffma2(unsigned long long& acc,
                                      unsigned long long a,
                                      unsigned long long b)
{
    asm("fma.rn.f32x2 %0, %1, %2, %0;" : "+l"(acc) : "l"(a), "l"(b));
}
__device__ __forceinline__ float hsum2(unsigned long long a)
{
    float2 f = *reinterpret_cast<float2*>(&a);
    return f.x + f.y;
}

// ---------------------------------------------------------------------------
// Pass 1: 4 chunks per 512-thread block (warp-group g -> chunk g).
// One shared copy of the 3 transposed pair-packed W matrices (198KB);
// 16 warps/SM for latency hiding. Packed FFMA2 GEMV + in-register scan.
// ---------------------------------------------------------------------------
#define SMEM1_BYTES (3 * 64 * 129 * 8 + 4 * 8 * 128 * 4)   // 214528

__global__ __launch_bounds__(512, 1)
void pass1_kernel(const float* __restrict__ x,
                  const float* __restrict__ log_A,
                  const float* __restrict__ W_B,
                  const float* __restrict__ W_C,
                  const float* __restrict__ W_dt,
                  const float* __restrict__ b_dt)
{
    extern __shared__ float sm[];
    unsigned long long* sWd2 = (unsigned long long*)sm;               // [64*129]
    unsigned long long* sWb2 = sWd2 + 64 * 129;
    unsigned long long* sWc2 = sWb2 + 64 * 129;
    float* sx = (float*)(sWc2 + 64 * 129);                            // [4][8*128]

    const int b = blockIdx.y, tid = threadIdx.x;
    const int ch = tid >> 7;              // 0..3: which chunk this thread serves
    const int s  = tid & 127;
    const int c  = blockIdx.x * 4 + ch;

    // Transposed pair layout: sW2[kp*129 + s] = W[s*128 + 2kp .. 2kp+1]
    {
        const unsigned long long* Wd = (const unsigned long long*)W_dt;
        const unsigned long long* Wb = (const unsigned long long*)W_B;
        const unsigned long long* Wc = (const unsigned long long*)W_C;
        for (int i = tid; i < 128 * 64; i += 512) {
            int ss = i >> 6, kp = i & 63;
            sWd2[kp * 129 + ss] = Wd[i];
            sWb2[kp * 129 + ss] = Wb[i];
            sWc2[kp * 129 + ss] = Wc[i];
        }
    }

    const float A_s = -fminf(__expf(log_A[s]), 10.0f);
    const float bd  = b_dt[s];

    float cs = 0.0f, acc = 0.0f;
    const size_t gb = ((size_t)b * NT + (size_t)c * CK) * NS + s;

    // 4 chunks are contiguous tokens: one base pointer
    const float4* xgs = (const float4*)(x + ((size_t)b * NT + (size_t)(blockIdx.x * 4) * CK) * ND);
    float4* sx4 = (float4*)sx;
    const float* mysx = sx + ch * (8 * 128);

    for (int tt = 0; tt < 8; ++tt) {
        __syncthreads();   // previous tile fully consumed
        // stage 8-token x tiles for all 4 chunks: 1024 float4, 2 per thread
#pragma unroll
        for (int r = 0; r < 2; ++r) {
            int f = tid + r * 512;             // [0,1024)
            int chl = f >> 8, w = f & 255;     // chunk, token*32+k4
            sx4[f] = xgs[(size_t)chl * 2048 + tt * 256 + w];
        }
        __syncthreads();

        unsigned long long a2d[8], a2b[8], a2c[8];
#pragma unroll
        for (int i = 0; i < 8; ++i) { a2d[i] = 0ULL; a2b[i] = 0ULL; a2c[i] = 0ULL; }

#pragma unroll 4
        for (int kp = 0; kp < 64; kp += 2) {
            unsigned long long wd0 = sWd2[(kp + 0) * 129 + s];
            unsigned long long wd1 = sWd2[(kp + 1) * 129 + s];
            unsigned long long wb0 = sWb2[(kp + 0) * 129 + s];
            unsigned long long wb1 = sWb2[(kp + 1) * 129 + s];
            unsigned long long wc0 = sWc2[(kp + 0) * 129 + s];
            unsigned long long wc1 = sWc2[(kp + 1) * 129 + s];
#pragma unroll
            for (int i = 0; i < 8; ++i) {
                ulonglong2 xq = *(const ulonglong2*)&mysx[i * 128 + kp * 2];
                ffma2(a2d[i], xq.x, wd0); ffma2(a2d[i], xq.y, wd1);
                ffma2(a2b[i], xq.x, wb0); ffma2(a2b[i], xq.y, wb1);
                ffma2(a2c[i], xq.x, wc0); ffma2(a2c[i], xq.y, wc1);
            }
        }

        // Sequential (token-order) clipped scan for state s
#pragma unroll
        for (int i = 0; i < 8; ++i) {
            const int t = tt * 8 + i;
            float v  = hsum2(a2d[i]) + bd;
            float sp = (v > 15.0f) ? v : __logf(1.0f + __expf(v));
            float dt = fminf(sp, 1.0f);
            float la = fminf(fmaxf(dt * A_s, -0.5f), 0.0f);
            float u  = hsum2(a2b[i]) * dt;
            cs += la;
            float lp = fminf(fmaxf(cs, -30.0f), 0.0f);
            float p  = __expf(lp);
            acc = fmaf(u, __expf(-lp), acc);
            const size_t gi = gb + (size_t)t * NS;
            g_C[gi]  = hsum2(a2c[i]);
            g_p[gi]  = p;
            g_hl[gi] = p * acc;
        }
    }
}

// ---------------------------------------------------------------------------
// Pass 2: inter-chunk prefix scan of chunk-tail states.
// ---------------------------------------------------------------------------
#define SMEM2_BYTES (2 * 128 * 128 * 4)

__global__ __launch_bounds__(128)
void pass2_kernel()
{
    extern __shared__ float sm[];
    float* sP = sm;
    float* sH = sm + 128 * 128;
    const int b = blockIdx.x, tid = threadIdx.x;

    const size_t bb = (size_t)b * NT * NS;
    for (int i = tid; i < 128 * 128; i += 128) {
        int c = i >> 7, s = i & 127;
        size_t gi = bb + (size_t)(c * CK + (CK - 1)) * NS + s;
        sP[i] = g_p[gi];
        sH[i] = g_hl[gi];
    }
    __syncthreads();

    const int s = tid;
    float h0 = 0.0f;
    const size_t hb = (size_t)b * NC * NS + s;
#pragma unroll 8
    for (int c = 0; c < NC; ++c) {
        g_h0[hb + (size_t)c * NS] = h0;
        h0 = fmaf(sP[c * 128 + s], h0, sH[c * 128 + s]);
    }
}

// ---------------------------------------------------------------------------
// Pass 3: h = hl + p*h0; y = sum_s C*h; out = h @ W_out^T + y * x[...,0]
// 256 threads: (d = tid&127, token-half = tid>>7). Packed FFMA2 GEMM.
// ---------------------------------------------------------------------------
#define SMEM3_BYTES (64 * 129 * 8 + 64 * 132 * 4 + (64 + 128 + 64) * 4)

__global__ __launch_bounds__(256)
void pass3_kernel(const float* __restrict__ x,
                  const float* __restrict__ W_out,
                  float* __restrict__ out)
{
    extern __shared__ float sm[];
    unsigned long long* sWo2 = (unsigned long long*)sm;   // [sp*129 + d]
    float* sh  = (float*)(sWo2 + 64 * 129);               // [t*132 + s]
    float* sy  = sh  + 64 * 132;
    float* sh0 = sy  + 64;
    float* sx0 = sh0 + 128;

    const int c = blockIdx.x, b = blockIdx.y, tid = threadIdx.x;
    const size_t tbase = (size_t)b * NT + (size_t)c * CK;
    const size_t gbase = tbase * NS;

    // sWo2[sp*129 + d] = (W_out[d][2sp], W_out[d][2sp+1])
    {
        const unsigned long long* Wo = (const unsigned long long*)W_out;
        for (int i = tid; i < 128 * 64; i += 256) {
            int d = i >> 6, sp = i & 63;
            sWo2[sp * 129 + d] = Wo[i];
        }
    }
    if (tid < 128) sh0[tid] = g_h0[((size_t)b * NC + c) * NS + tid];
    else if (tid < 192) sx0[tid - 128] = x[(tbase + tid - 128) * ND];
    __syncthreads();

    for (int i = tid; i < 64 * 128; i += 256) {
        int t = i >> 7, s = i & 127;
        sh[t * 132 + s] = fmaf(g_p[gbase + i], sh0[s], g_hl[gbase + i]);
    }
    __syncthreads();

    // y[t] = sum_s C[t][s] * h[t][s]  (8 warps -> 8 tokens each)
    {
        const int w = tid >> 5, l = tid & 31;
        const float4* C4 = (const float4*)(g_C + gbase);
        for (int t = w * 8; t < w * 8 + 8; ++t) {
            float4 cv = C4[t * 32 + l];
            const float* hr = &sh[t * 132 + l * 4];
            float v = cv.x * hr[0] + cv.y * hr[1] + cv.z * hr[2] + cv.w * hr[3];
#pragma unroll
            for (int o = 16; o; o >>= 1) v += __shfl_xor_sync(0xFFFFFFFFu, v, o);
            if (l == 0) sy[t] = v;
        }
    }
    __syncthreads();

    // out GEMM with packed FFMA2
    const int d = tid & 127;
    const int th = tid >> 7;
    float* outp = out + gbase + d;
    for (int tt = th * 4; tt < th * 4 + 4; ++tt) {
        unsigned long long acc2[8];
#pragma unroll
        for (int i = 0; i < 8; ++i) acc2[i] = 0ULL;
#pragma unroll 4
        for (int sp = 0; sp < 64; sp += 2) {
            unsigned long long w0 = sWo2[(sp + 0) * 129 + d];
            unsigned long long w1 = sWo2[(sp + 1) * 129 + d];
#pragma unroll
            for (int i = 0; i < 8; ++i) {
                ulonglong2 hq = *(const ulonglong2*)&sh[(tt * 8 + i) * 132 + sp * 2];
                ffma2(acc2[i], hq.x, w0);
                ffma2(acc2[i], hq.y, w1);
            }
        }
#pragma unroll
        for (int i = 0; i < 8; ++i) {
            const int t = tt * 8 + i;
            outp[(size_t)t * NS] = hsum2(acc2[i]) + sy[t] * sx0[t];
        }
    }
}

// ---------------------------------------------------------------------------
extern "C" void kernel_launch(void* const* d_in, const int* in_sizes, int n_in,
                              void* d_out, int out_size)
{
    const float* x     = (const float*)d_in[0];
    const float* log_A = (const float*)d_in[1];
    const float* W_B   = (const float*)d_in[2];
    const float* W_C   = (const float*)d_in[3];
    const float* W_dt  = (const float*)d_in[4];
    const float* b_dt  = (const float*)d_in[5];
    const float* W_out = (const float*)d_in[6];
    float* out = (float*)d_out;

    cudaFuncSetAttribute(pass1_kernel, cudaFuncAttributeMaxDynamicSharedMemorySize, SMEM1_BYTES);
    cudaFuncSetAttribute(pass2_kernel, cudaFuncAttributeMaxDynamicSharedMemorySize, SMEM2_BYTES);
    cudaFuncSetAttribute(pass3_kernel, cudaFuncAttributeMaxDynamicSharedMemorySize, SMEM3_BYTES);

    pass1_kernel<<<dim3(NC / 4, NB), 512, SMEM1_BYTES>>>(x, log_A, W_B, W_C, W_dt, b_dt);
    pass2_kernel<<<NB, 128, SMEM2_BYTES>>>();
    pass3_kernel<<<dim3(NC, NB), 256, SMEM3_BYTES>>>(x, W_out, out);
}

// round 6
// speedup vs baseline: 2.0314x; 1.2396x over previous
#include <cuda_runtime.h>
#include <cuda_bf16.h>
#include <cstdint>
#include <cstddef>

#define NB 8
#define NT 8192
#define ND 128
#define NS 128
#define CK 64
#define NC (NT / CK)   // 128

// Scratch (allocation-free rule: __device__ globals)
__device__ float g_hl[(size_t)NB * NT * NS];
__device__ float g_p [(size_t)NB * NT * NS];
__device__ float g_C [(size_t)NB * NT * NS];
__device__ float g_h0[(size_t)NB * NC * NS];
// Pre-swizzled bf16 hi/lo W tiles: [mat][term(hi,lo)][khalf] each 128 rows x 64 k bf16 (16KB)
__device__ __align__(16) unsigned char g_Wb[3 * 2 * 2 * 16384];

__device__ __forceinline__ uint32_t smem_u32(const void* p) {
    uint32_t a;
    asm("{ .reg .u64 t; cvta.to.shared.u64 t, %1; cvt.u32.u64 %0, t; }" : "=r"(a) : "l"(p));
    return a;
}
__device__ __forceinline__ uint32_t sw128(uint32_t off) { return off ^ ((off >> 3) & 0x70); }

__device__ __forceinline__ void ldsm_x4(uint32_t* r, uint32_t addr) {
    asm volatile("ldmatrix.sync.aligned.m8n8.x4.shared.b16 {%0,%1,%2,%3}, [%4];"
        : "=r"(r[0]), "=r"(r[1]), "=r"(r[2]), "=r"(r[3]) : "r"(addr));
}
__device__ __forceinline__ void ldsm_x2(uint32_t* r, uint32_t addr) {
    asm volatile("ldmatrix.sync.aligned.m8n8.x2.shared.b16 {%0,%1}, [%2];"
        : "=r"(r[0]), "=r"(r[1]) : "r"(addr));
}
__device__ __forceinline__ void mma_bf16(float* d, const uint32_t* a, const uint32_t* b) {
    asm volatile("mma.sync.aligned.m16n8k16.row.col.f32.bf16.bf16.f32 "
        "{%0,%1,%2,%3}, {%4,%5,%6,%7}, {%8,%9}, {%0,%1,%2,%3};"
        : "+f"(d[0]), "+f"(d[1]), "+f"(d[2]), "+f"(d[3])
        : "r"(a[0]), "r"(a[1]), "r"(a[2]), "r"(a[3]), "r"(b[0]), "r"(b[1]));
}

// ---------------------------------------------------------------------------
// Prep: convert W (3 mats) to swizzled bf16 hi/lo k-half tiles in global.
// ---------------------------------------------------------------------------
__global__ void prep_kernel(const float* __restrict__ W_B,
                            const float* __restrict__ W_C,
                            const float* __restrict__ W_dt)
{
    int e = blockIdx.x * 256 + threadIdx.x;
    if (e >= 3 * 16384) return;
    int mat = e >> 14, rk = e & 16383, r = rk >> 7, k = rk & 127;
    const float* W = (mat == 0) ? W_dt : (mat == 1) ? W_B : W_C;
    float w = W[rk];
    __nv_bfloat16 hi = __float2bfloat16(w);
    __nv_bfloat16 lo = __float2bfloat16(w - __bfloat162float(hi));
    int half = k >> 6, kl = k & 63;
    uint32_t off = sw128((uint32_t)(r * 128 + kl * 2));
    *(__nv_bfloat16*)&g_Wb[((mat * 2 + 0) * 2 + half) * 16384 + off] = hi;
    *(__nv_bfloat16*)&g_Wb[((mat * 2 + 1) * 2 + half) * 16384 + off] = lo;
}

// ---------------------------------------------------------------------------
// Pass 1 (HMMA): per-chunk CTA (128 thr). X chunk -> bf16 hi/lo swizzled smem;
// per mat: stage W tiles, mma.sync m16n8k16 x (2m x 8n x 8k x 3 terms), dump
// D[s][t] to smem; then per-state register scan over 64 tokens.
// smem: X 32KB | W 64KB | D 3*128*66*4 = 99KB  -> 199680 B
// ---------------------------------------------------------------------------
#define SM_X   0
#define SM_W   32768
#define SM_D   98304
#define SDS    66
#define SMEM1_BYTES (98304 + 3 * 128 * SDS * 4)

__global__ __launch_bounds__(128)
void pass1_mma(const float* __restrict__ x,
               const float* __restrict__ log_A,
               const float* __restrict__ b_dt)
{
    extern __shared__ unsigned char smraw[];
    const uint32_t sbase = smem_u32(smraw);
    float* sD = (float*)(smraw + SM_D);
    const int c = blockIdx.x, b = blockIdx.y, tid = threadIdx.x;
    const int wid = tid >> 5, lane = tid & 31;

    // ---- Phase A: convert X chunk (64 tok x 128) to bf16 hi/lo swizzled tiles
    {
        const float4* xg = (const float4*)(x + ((size_t)b * NT + (size_t)c * CK) * ND);
        unsigned char* sX = smraw + SM_X;
#pragma unroll
        for (int j = 0; j < 16; ++j) {
            int idx = tid + 128 * j;                 // 2048 float4
            float4 v = xg[idx];
            int token = idx >> 5, k4 = idx & 31;
            int half = k4 >> 4;
            uint32_t off = (uint32_t)(token * 128) +
                           (((uint32_t)(k4 & 15) * 8) ^ ((uint32_t)(token & 7) << 4));
            __nv_bfloat162 h01 = __float22bfloat162_rn(make_float2(v.x, v.y));
            __nv_bfloat162 h23 = __float22bfloat162_rn(make_float2(v.z, v.w));
            __nv_bfloat162 l01 = __float22bfloat162_rn(make_float2(
                v.x - __bfloat162float(h01.x), v.y - __bfloat162float(h01.y)));
            __nv_bfloat162 l23 = __float22bfloat162_rn(make_float2(
                v.z - __bfloat162float(h23.x), v.w - __bfloat162float(h23.y)));
            *(__nv_bfloat162*)(sX + half * 8192 + off)             = h01;
            *(__nv_bfloat162*)(sX + half * 8192 + off + 4)         = h23;
            *(__nv_bfloat162*)(sX + 16384 + half * 8192 + off)     = l01;
            *(__nv_bfloat162*)(sX + 16384 + half * 8192 + off + 4) = l23;
        }
    }

    // Per-lane ldmatrix address components (simplified SW128: xor = (row&7)<<4)
    const int s0 = wid * 32;
    const uint32_t aj = lane >> 3, ar = lane & 7;          // A: j=matrix idx, r=row-in-8
    const uint32_t arow_lo = (aj & 1) * 8 + ar;            // + mt*16 + s0
    const uint32_t a_k16   = (aj >> 1) * 16;               // bytes: +8 bf16 cols for j>=2
    const uint32_t a_xor   = ar << 4;
    const uint32_t a_rb0 = (s0 + 0  + arow_lo) * 128;
    const uint32_t a_rb1 = (s0 + 16 + arow_lo) * 128;
    const uint32_t bj = (lane >> 3) & 1, br = lane & 7;    // B lanes 0-15 meaningful
    const uint32_t b_k16 = bj * 16;
    const uint32_t b_xor = br << 4;
    const uint32_t b_rb  = br * 128;                        // + nt*1024

    // ---- Phase B: 3 mats
    for (int mat = 0; mat < 3; ++mat) {
        __syncthreads();   // previous consumers done (X convert done / prev mat LDSM done)
        // stage W tiles for this mat: 64KB global -> smem
        {
            const float4* src = (const float4*)(g_Wb + (size_t)mat * 65536);
            float4* dst = (float4*)(smraw + SM_W);
#pragma unroll
            for (int j = 0; j < 32; ++j) dst[tid + 128 * j] = src[tid + 128 * j];
        }
        __syncthreads();

        float acc[2][8][4];
#pragma unroll
        for (int mt = 0; mt < 2; ++mt)
#pragma unroll
            for (int nt = 0; nt < 8; ++nt)
#pragma unroll
                for (int q = 0; q < 4; ++q) acc[mt][nt][q] = 0.0f;

        for (int term = 0; term < 3; ++term) {
            const uint32_t ta = (term == 2) ? 1u : 0u;   // W lo only term 2
            const uint32_t tb = (term == 1) ? 1u : 0u;   // X lo only term 1
            const uint32_t wbase = sbase + SM_W + ta * 32768;
            const uint32_t xbase = sbase + SM_X + tb * 16384;
#pragma unroll
            for (int kt = 0; kt < 8; ++kt) {
                const uint32_t half = kt >> 2;
                const uint32_t klo2 = (kt & 3) * 32;
                const uint32_t wb = wbase + half * 16384;
                const uint32_t xb = xbase + half * 8192;
                uint32_t a0[4], a1[4], bfr[8][2];
                ldsm_x4(a0, wb + a_rb0 + ((klo2 + a_k16) ^ a_xor));
                ldsm_x4(a1, wb + a_rb1 + ((klo2 + a_k16) ^ a_xor));
#pragma unroll
                for (int nt = 0; nt < 8; ++nt)
                    ldsm_x2(bfr[nt], xb + b_rb + nt * 1024 + ((klo2 + b_k16) ^ b_xor));
#pragma unroll
                for (int nt = 0; nt < 8; ++nt) {
                    mma_bf16(acc[0][nt], a0, bfr[nt]);
                    mma_bf16(acc[1][nt], a1, bfr[nt]);
                }
            }
        }

        // write D fragments to sD[mat][s][t]
        float* dm = sD + mat * (128 * SDS);
        const int dr = lane >> 2, dc = (lane & 3) * 2;
#pragma unroll
        for (int mt = 0; mt < 2; ++mt) {
            const int sw = s0 + mt * 16 + dr;
#pragma unroll
            for (int nt = 0; nt < 8; ++nt) {
                const int t0 = nt * 8 + dc;
                *(float2*)&dm[sw * SDS + t0]       = make_float2(acc[mt][nt][0], acc[mt][nt][1]);
                *(float2*)&dm[(sw + 8) * SDS + t0] = make_float2(acc[mt][nt][2], acc[mt][nt][3]);
            }
        }
    }
    __syncthreads();

    // ---- Phase C: per-state clipped scan over 64 tokens
    {
        const int s = tid;
        const float A_s = -fminf(__expf(log_A[s]), 10.0f);
        const float bd  = b_dt[s];
        float cs = 0.0f, acc = 0.0f;
        const size_t gb = ((size_t)b * NT + (size_t)c * CK) * NS + s;
        const float* rdt = sD + 0 * (128 * SDS) + s * SDS;
        const float* rbx = sD + 1 * (128 * SDS) + s * SDS;
        const float* rc  = sD + 2 * (128 * SDS) + s * SDS;
#pragma unroll 4
        for (int t = 0; t < 64; ++t) {
            float v  = rdt[t] + bd;
            float sp = (v > 15.0f) ? v : __logf(1.0f + __expf(v));
            float dt = fminf(sp, 1.0f);
            float la = fminf(fmaxf(dt * A_s, -0.5f), 0.0f);
            float u  = rbx[t] * dt;
            cs += la;
            float lp = fminf(fmaxf(cs, -30.0f), 0.0f);
            float p  = __expf(lp);
            acc = fmaf(u, __expf(-lp), acc);
            const size_t gi = gb + (size_t)t * NS;
            g_C[gi]  = rc[t];
            g_p[gi]  = p;
            g_hl[gi] = p * acc;
        }
    }
}

// ---------------------------------------------------------------------------
// Pass 2: inter-chunk prefix scan (unchanged)
// ---------------------------------------------------------------------------
#define SMEM2_BYTES (2 * 128 * 128 * 4)

__global__ __launch_bounds__(128)
void pass2_kernel()
{
    extern __shared__ float smf[];
    float* sP = smf;
    float* sH = smf + 128 * 128;
    const int b = blockIdx.x, tid = threadIdx.x;

    const size_t bb = (size_t)b * NT * NS;
    for (int i = tid; i < 128 * 128; i += 128) {
        int c = i >> 7, s = i & 127;
        size_t gi = bb + (size_t)(c * CK + (CK - 1)) * NS + s;
        sP[i] = g_p[gi];
        sH[i] = g_hl[gi];
    }
    __syncthreads();

    const int s = tid;
    float h0 = 0.0f;
    const size_t hb = (size_t)b * NC * NS + s;
#pragma unroll 8
    for (int c = 0; c < NC; ++c) {
        g_h0[hb + (size_t)c * NS] = h0;
        h0 = fmaf(sP[c * 128 + s], h0, sH[c * 128 + s]);
    }
}

// ---------------------------------------------------------------------------
// Pass 3: unchanged FFMA2 version
// ---------------------------------------------------------------------------
__device__ __forceinline__ void ffma2(unsigned long long& acc,
                                      unsigned long long a,
                                      unsigned long long b)
{
    asm("fma.rn.f32x2 %0, %1, %2, %0;" : "+l"(acc) : "l"(a), "l"(b));
}
__device__ __forceinline__ float hsum2(unsigned long long a)
{
    float2 f = *reinterpret_cast<float2*>(&a);
    return f.x + f.y;
}

#define SMEM3_BYTES (64 * 129 * 8 + 64 * 132 * 4 + (64 + 128 + 64) * 4)

__global__ __launch_bounds__(256)
void pass3_kernel(const float* __restrict__ x,
                  const float* __restrict__ W_out,
                  float* __restrict__ out)
{
    extern __shared__ float smf[];
    unsigned long long* sWo2 = (unsigned long long*)smf;
    float* sh  = (float*)(sWo2 + 64 * 129);
    float* sy  = sh  + 64 * 132;
    float* sh0 = sy  + 64;
    float* sx0 = sh0 + 128;

    const int c = blockIdx.x, b = blockIdx.y, tid = threadIdx.x;
    const size_t tbase = (size_t)b * NT + (size_t)c * CK;
    const size_t gbase = tbase * NS;

    {
        const unsigned long long* Wo = (const unsigned long long*)W_out;
        for (int i = tid; i < 128 * 64; i += 256) {
            int d = i >> 6, sp = i & 63;
            sWo2[sp * 129 + d] = Wo[i];
        }
    }
    if (tid < 128) sh0[tid] = g_h0[((size_t)b * NC + c) * NS + tid];
    else if (tid < 192) sx0[tid - 128] = x[(tbase + tid - 128) * ND];
    __syncthreads();

    for (int i = tid; i < 64 * 128; i += 256) {
        int t = i >> 7, s = i & 127;
        sh[t * 132 + s] = fmaf(g_p[gbase + i], sh0[s], g_hl[gbase + i]);
    }
    __syncthreads();

    {
        const int w = tid >> 5, l = tid & 31;
        const float4* C4 = (const float4*)(g_C + gbase);
        for (int t = w * 8; t < w * 8 + 8; ++t) {
            float4 cv = C4[t * 32 + l];
            const float* hr = &sh[t * 132 + l * 4];
            float v = cv.x * hr[0] + cv.y * hr[1] + cv.z * hr[2] + cv.w * hr[3];
#pragma unroll
            for (int o = 16; o; o >>= 1) v += __shfl_xor_sync(0xFFFFFFFFu, v, o);
            if (l == 0) sy[t] = v;
        }
    }
    __syncthreads();

    const int d = tid & 127;
    const int th = tid >> 7;
    float* outp = out + gbase + d;
    for (int tt = th * 4; tt < th * 4 + 4; ++tt) {
        unsigned long long acc2[8];
#pragma unroll
        for (int i = 0; i < 8; ++i) acc2[i] = 0ULL;
#pragma unroll 4
        for (int sp = 0; sp < 64; sp += 2) {
            unsigned long long w0 = sWo2[(sp + 0) * 129 + d];
            unsigned long long w1 = sWo2[(sp + 1) * 129 + d];
#pragma unroll
            for (int i = 0; i < 8; ++i) {
                ulonglong2 hq = *(const ulonglong2*)&sh[(tt * 8 + i) * 132 + sp * 2];
                ffma2(acc2[i], hq.x, w0);
                ffma2(acc2[i], hq.y, w1);
            }
        }
#pragma unroll
        for (int i = 0; i < 8; ++i) {
            const int t = tt * 8 + i;
            outp[(size_t)t * NS] = hsum2(acc2[i]) + sy[t] * sx0[t];
        }
    }
}

// ---------------------------------------------------------------------------
extern "C" void kernel_launch(void* const* d_in, const int* in_sizes, int n_in,
                              void* d_out, int out_size)
{
    const float* x     = (const float*)d_in[0];
    const float* log_A = (const float*)d_in[1];
    const float* W_B   = (const float*)d_in[2];
    const float* W_C   = (const float*)d_in[3];
    const float* W_dt  = (const float*)d_in[4];
    const float* b_dt  = (const float*)d_in[5];
    const float* W_out = (const float*)d_in[6];
    float* out = (float*)d_out;

    cudaFuncSetAttribute(pass1_mma, cudaFuncAttributeMaxDynamicSharedMemorySize, SMEM1_BYTES);
    cudaFuncSetAttribute(pass2_kernel, cudaFuncAttributeMaxDynamicSharedMemorySize, SMEM2_BYTES);
    cudaFuncSetAttribute(pass3_kernel, cudaFuncAttributeMaxDynamicSharedMemorySize, SMEM3_BYTES);

    prep_kernel<<<192, 256>>>(W_B, W_C, W_dt);
    pass1_mma<<<dim3(NC, NB), 128, SMEM1_BYTES>>>(x, log_A, b_dt);
    pass2_kernel<<<NB, 128, SMEM2_BYTES>>>();
    pass3_kernel<<<dim3(NC, NB), 256, SMEM3_BYTES>>>(x, W_out, out);
}

// round 7
// speedup vs baseline: 2.4290x; 1.1957x over previous
#include <cuda_runtime.h>
#include <cuda_bf16.h>
#include <cstdint>
#include <cstddef>

#define NB 8
#define NT 8192
#define ND 128
#define NS 128
#define CK 64
#define NC (NT / CK)   // 128

// Scratch (allocation-free rule: __device__ globals)
__device__ float g_hl[(size_t)NB * NT * NS];
__device__ float g_p [(size_t)NB * NT * NS];
__device__ float g_C [(size_t)NB * NT * NS];
__device__ float g_h0[(size_t)NB * NC * NS];
// Pre-swizzled bf16 hi/lo tiles: [mat(dt,B,C,out)][term(hi,lo)][khalf] 128r x 64k (16KB)
__device__ __align__(16) unsigned char g_Wb[4 * 2 * 2 * 16384];

__device__ __forceinline__ uint32_t smem_u32(const void* p) {
    uint32_t a;
    asm("{ .reg .u64 t; cvta.to.shared.u64 t, %1; cvt.u32.u64 %0, t; }" : "=r"(a) : "l"(p));
    return a;
}
__device__ __forceinline__ uint32_t sw128(uint32_t off) { return off ^ ((off >> 3) & 0x70); }

__device__ __forceinline__ void ldsm_x4(uint32_t* r, uint32_t addr) {
    asm volatile("ldmatrix.sync.aligned.m8n8.x4.shared.b16 {%0,%1,%2,%3}, [%4];"
        : "=r"(r[0]), "=r"(r[1]), "=r"(r[2]), "=r"(r[3]) : "r"(addr));
}
__device__ __forceinline__ void ldsm_x2(uint32_t* r, uint32_t addr) {
    asm volatile("ldmatrix.sync.aligned.m8n8.x2.shared.b16 {%0,%1}, [%2];"
        : "=r"(r[0]), "=r"(r[1]) : "r"(addr));
}
__device__ __forceinline__ void mma_bf16(float* d, const uint32_t* a, const uint32_t* b) {
    asm volatile("mma.sync.aligned.m16n8k16.row.col.f32.bf16.bf16.f32 "
        "{%0,%1,%2,%3}, {%4,%5,%6,%7}, {%8,%9}, {%0,%1,%2,%3};"
        : "+f"(d[0]), "+f"(d[1]), "+f"(d[2]), "+f"(d[3])
        : "r"(a[0]), "r"(a[1]), "r"(a[2]), "r"(a[3]), "r"(b[0]), "r"(b[1]));
}

// ---------------------------------------------------------------------------
// Prep: convert 4 weight mats to swizzled bf16 hi/lo k-half tiles in global.
// ---------------------------------------------------------------------------
__global__ void prep_kernel(const float* __restrict__ W_B,
                            const float* __restrict__ W_C,
                            const float* __restrict__ W_dt,
                            const float* __restrict__ W_out)
{
    int e = blockIdx.x * 256 + threadIdx.x;
    if (e >= 4 * 16384) return;
    int mat = e >> 14, rk = e & 16383, r = rk >> 7, k = rk & 127;
    const float* W = (mat == 0) ? W_dt : (mat == 1) ? W_B : (mat == 2) ? W_C : W_out;
    float w = W[rk];
    __nv_bfloat16 hi = __float2bfloat16(w);
    __nv_bfloat16 lo = __float2bfloat16(w - __bfloat162float(hi));
    int half = k >> 6, kl = k & 63;
    uint32_t off = sw128((uint32_t)(r * 128 + kl * 2));
    *(__nv_bfloat16*)&g_Wb[((mat * 2 + 0) * 2 + half) * 16384 + off] = hi;
    *(__nv_bfloat16*)&g_Wb[((mat * 2 + 1) * 2 + half) * 16384 + off] = lo;
}

// ---------------------------------------------------------------------------
// Pass 1 (HMMA): unchanged from R6.
// ---------------------------------------------------------------------------
#define SM_X   0
#define SM_W   32768
#define SM_D   98304
#define SDS    66
#define SMEM1_BYTES (98304 + 3 * 128 * SDS * 4)

__global__ __launch_bounds__(128)
void pass1_mma(const float* __restrict__ x,
               const float* __restrict__ log_A,
               const float* __restrict__ b_dt)
{
    extern __shared__ unsigned char smraw[];
    const uint32_t sbase = smem_u32(smraw);
    float* sD = (float*)(smraw + SM_D);
    const int c = blockIdx.x, b = blockIdx.y, tid = threadIdx.x;
    const int wid = tid >> 5, lane = tid & 31;

    {
        const float4* xg = (const float4*)(x + ((size_t)b * NT + (size_t)c * CK) * ND);
        unsigned char* sX = smraw + SM_X;
#pragma unroll
        for (int j = 0; j < 16; ++j) {
            int idx = tid + 128 * j;
            float4 v = xg[idx];
            int token = idx >> 5, k4 = idx & 31;
            int half = k4 >> 4;
            uint32_t off = (uint32_t)(token * 128) +
                           (((uint32_t)(k4 & 15) * 8) ^ ((uint32_t)(token & 7) << 4));
            __nv_bfloat162 h01 = __float22bfloat162_rn(make_float2(v.x, v.y));
            __nv_bfloat162 h23 = __float22bfloat162_rn(make_float2(v.z, v.w));
            __nv_bfloat162 l01 = __float22bfloat162_rn(make_float2(
                v.x - __bfloat162float(h01.x), v.y - __bfloat162float(h01.y)));
            __nv_bfloat162 l23 = __float22bfloat162_rn(make_float2(
                v.z - __bfloat162float(h23.x), v.w - __bfloat162float(h23.y)));
            *(__nv_bfloat162*)(sX + half * 8192 + off)             = h01;
            *(__nv_bfloat162*)(sX + half * 8192 + off + 4)         = h23;
            *(__nv_bfloat162*)(sX + 16384 + half * 8192 + off)     = l01;
            *(__nv_bfloat162*)(sX + 16384 + half * 8192 + off + 4) = l23;
        }
    }

    const int s0 = wid * 32;
    const uint32_t aj = lane >> 3, ar = lane & 7;
    const uint32_t arow_lo = (aj & 1) * 8 + ar;
    const uint32_t a_k16   = (aj >> 1) * 16;
    const uint32_t a_xor   = ar << 4;
    const uint32_t a_rb0 = (s0 + 0  + arow_lo) * 128;
    const uint32_t a_rb1 = (s0 + 16 + arow_lo) * 128;
    const uint32_t bj = (lane >> 3) & 1, br = lane & 7;
    const uint32_t b_k16 = bj * 16;
    const uint32_t b_xor = br << 4;
    const uint32_t b_rb  = br * 128;

    for (int mat = 0; mat < 3; ++mat) {
        __syncthreads();
        {
            const float4* src = (const float4*)(g_Wb + (size_t)mat * 65536);
            float4* dst = (float4*)(smraw + SM_W);
#pragma unroll
            for (int j = 0; j < 32; ++j) dst[tid + 128 * j] = src[tid + 128 * j];
        }
        __syncthreads();

        float acc[2][8][4];
#pragma unroll
        for (int mt = 0; mt < 2; ++mt)
#pragma unroll
            for (int nt = 0; nt < 8; ++nt)
#pragma unroll
                for (int q = 0; q < 4; ++q) acc[mt][nt][q] = 0.0f;

        for (int term = 0; term < 3; ++term) {
            const uint32_t ta = (term == 2) ? 1u : 0u;
            const uint32_t tb = (term == 1) ? 1u : 0u;
            const uint32_t wbase = sbase + SM_W + ta * 32768;
            const uint32_t xbase = sbase + SM_X + tb * 16384;
#pragma unroll
            for (int kt = 0; kt < 8; ++kt) {
                const uint32_t half = kt >> 2;
                const uint32_t klo2 = (kt & 3) * 32;
                const uint32_t wb = wbase + half * 16384;
                const uint32_t xb = xbase + half * 8192;
                uint32_t a0[4], a1[4], bfr[8][2];
                ldsm_x4(a0, wb + a_rb0 + ((klo2 + a_k16) ^ a_xor));
                ldsm_x4(a1, wb + a_rb1 + ((klo2 + a_k16) ^ a_xor));
#pragma unroll
                for (int nt = 0; nt < 8; ++nt)
                    ldsm_x2(bfr[nt], xb + b_rb + nt * 1024 + ((klo2 + b_k16) ^ b_xor));
#pragma unroll
                for (int nt = 0; nt < 8; ++nt) {
                    mma_bf16(acc[0][nt], a0, bfr[nt]);
                    mma_bf16(acc[1][nt], a1, bfr[nt]);
                }
            }
        }

        float* dm = sD + mat * (128 * SDS);
        const int dr = lane >> 2, dc = (lane & 3) * 2;
#pragma unroll
        for (int mt = 0; mt < 2; ++mt) {
            const int sw = s0 + mt * 16 + dr;
#pragma unroll
            for (int nt = 0; nt < 8; ++nt) {
                const int t0 = nt * 8 + dc;
                *(float2*)&dm[sw * SDS + t0]       = make_float2(acc[mt][nt][0], acc[mt][nt][1]);
                *(float2*)&dm[(sw + 8) * SDS + t0] = make_float2(acc[mt][nt][2], acc[mt][nt][3]);
            }
        }
    }
    __syncthreads();

    {
        const int s = tid;
        const float A_s = -fminf(__expf(log_A[s]), 10.0f);
        const float bd  = b_dt[s];
        float cs = 0.0f, acc = 0.0f;
        const size_t gb = ((size_t)b * NT + (size_t)c * CK) * NS + s;
        const float* rdt = sD + 0 * (128 * SDS) + s * SDS;
        const float* rbx = sD + 1 * (128 * SDS) + s * SDS;
        const float* rc  = sD + 2 * (128 * SDS) + s * SDS;
#pragma unroll 4
        for (int t = 0; t < 64; ++t) {
            float v  = rdt[t] + bd;
            float sp = (v > 15.0f) ? v : __logf(1.0f + __expf(v));
            float dt = fminf(sp, 1.0f);
            float la = fminf(fmaxf(dt * A_s, -0.5f), 0.0f);
            float u  = rbx[t] * dt;
            cs += la;
            float lp = fminf(fmaxf(cs, -30.0f), 0.0f);
            float p  = __expf(lp);
            acc = fmaf(u, __expf(-lp), acc);
            const size_t gi = gb + (size_t)t * NS;
            g_C[gi]  = rc[t];
            g_p[gi]  = p;
            g_hl[gi] = p * acc;
        }
    }
}

// ---------------------------------------------------------------------------
// Pass 2: inter-chunk prefix scan (unchanged)
// ---------------------------------------------------------------------------
#define SMEM2_BYTES (2 * 128 * 128 * 4)

__global__ __launch_bounds__(128)
void pass2_kernel()
{
    extern __shared__ float smf[];
    float* sP = smf;
    float* sH = smf + 128 * 128;
    const int b = blockIdx.x, tid = threadIdx.x;

    const size_t bb = (size_t)b * NT * NS;
    for (int i = tid; i < 128 * 128; i += 128) {
        int c = i >> 7, s = i & 127;
        size_t gi = bb + (size_t)(c * CK + (CK - 1)) * NS + s;
        sP[i] = g_p[gi];
        sH[i] = g_hl[gi];
    }
    __syncthreads();

    const int s = tid;
    float h0 = 0.0f;
    const size_t hb = (size_t)b * NC * NS + s;
#pragma unroll 8
    for (int c = 0; c < NC; ++c) {
        g_h0[hb + (size_t)c * NS] = h0;
        h0 = fmaf(sP[c * 128 + s], h0, sH[c * 128 + s]);
    }
}

// ---------------------------------------------------------------------------
// Pass 3 (HMMA): h = hl + p*h0 (fp32 + bf16 hi/lo tiles); y = sum_s C*h (fp32);
// out[d][t] = W_out h^T via mma; epilogue adds y[t]*x[t,0], coalesced store.
// smem: W 64KB | Hbf16 32KB | hf32/out 64x132x4 (shared region) | y/h0/x0
// ---------------------------------------------------------------------------
#define P3_W 0
#define P3_H 65536
#define P3_F 98304
#define P3S  132
#define P3_Y (98304 + 64 * P3S * 4)
#define SMEM3_BYTES (P3_Y + (64 + 128 + 64) * 4)

__global__ __launch_bounds__(128)
void pass3_mma(const float* __restrict__ x,
               float* __restrict__ out)
{
    extern __shared__ unsigned char smraw[];
    const uint32_t sbase = smem_u32(smraw);
    float* shf = (float*)(smraw + P3_F);    // fp32 h, later reused as out stage
    float* sy  = (float*)(smraw + P3_Y);
    float* sh0 = sy + 64;
    float* sx0 = sh0 + 128;
    const int c = blockIdx.x, b = blockIdx.y, tid = threadIdx.x;
    const int wid = tid >> 5, lane = tid & 31;
    const size_t tbase = (size_t)b * NT + (size_t)c * CK;
    const size_t gbase = tbase * NS;

    // Stage W_out hi/lo tiles (64KB)
    {
        const float4* src = (const float4*)(g_Wb + (size_t)3 * 65536);
        float4* dst = (float4*)(smraw + P3_W);
#pragma unroll
        for (int j = 0; j < 32; ++j) dst[tid + 128 * j] = src[tid + 128 * j];
    }
    sh0[tid] = g_h0[((size_t)b * NC + c) * NS + tid];
    if (tid < 64) sx0[tid] = x[(tbase + tid) * ND];
    __syncthreads();

    // Reconstruct h: fp32 into shf, bf16 hi/lo into swizzled tiles
    {
        unsigned char* sH = smraw + P3_H;
#pragma unroll
        for (int j = 0; j < 32; ++j) {
            int idx = tid + 128 * j;        // 4096 pairs
            int t = idx >> 6, sp = idx & 63;
            float2 pv = *(const float2*)&g_p [gbase + (size_t)t * NS + sp * 2];
            float2 hv = *(const float2*)&g_hl[gbase + (size_t)t * NS + sp * 2];
            float2 h;
            h.x = fmaf(pv.x, sh0[sp * 2],     hv.x);
            h.y = fmaf(pv.y, sh0[sp * 2 + 1], hv.y);
            *(float2*)&shf[t * P3S + sp * 2] = h;
            __nv_bfloat162 hi2 = __float22bfloat162_rn(h);
            __nv_bfloat162 lo2 = __float22bfloat162_rn(make_float2(
                h.x - __bfloat162float(hi2.x), h.y - __bfloat162float(hi2.y)));
            int half = sp >> 5, klp = sp & 31;
            uint32_t off = (uint32_t)(t * 128) + (((uint32_t)klp * 4) ^ ((uint32_t)(t & 7) << 4));
            *(__nv_bfloat162*)(sH + half * 8192 + off)         = hi2;
            *(__nv_bfloat162*)(sH + 16384 + half * 8192 + off) = lo2;
        }
    }
    __syncthreads();

    // y[t] = sum_s C[t][s]*h[t][s]  (4 warps x 16 tokens, exact fp32)
    {
        const float4* C4 = (const float4*)(g_C + gbase);
        for (int t = wid * 16; t < wid * 16 + 16; ++t) {
            float4 cv = C4[t * 32 + lane];
            const float* hr = &shf[t * P3S + lane * 4];
            float v = cv.x * hr[0] + cv.y * hr[1] + cv.z * hr[2] + cv.w * hr[3];
#pragma unroll
            for (int o = 16; o; o >>= 1) v += __shfl_xor_sync(0xFFFFFFFFu, v, o);
            if (lane == 0) sy[t] = v;
        }
    }
    __syncthreads();   // y done; shf region free for out staging

    // MMA: D[d][t] = W_out h^T (3-term bf16)
    {
        const int d0 = wid * 32;
        const uint32_t aj = lane >> 3, ar = lane & 7;
        const uint32_t arow_lo = (aj & 1) * 8 + ar;
        const uint32_t a_k16   = (aj >> 1) * 16;
        const uint32_t a_xor   = ar << 4;
        const uint32_t a_rb0 = (d0 + 0  + arow_lo) * 128;
        const uint32_t a_rb1 = (d0 + 16 + arow_lo) * 128;
        const uint32_t bj = (lane >> 3) & 1, br = lane & 7;
        const uint32_t b_k16 = bj * 16;
        const uint32_t b_xor = br << 4;
        const uint32_t b_rb  = br * 128;

        float acc[2][8][4];
#pragma unroll
        for (int mt = 0; mt < 2; ++mt)
#pragma unroll
            for (int nt = 0; nt < 8; ++nt)
#pragma unroll
                for (int q = 0; q < 4; ++q) acc[mt][nt][q] = 0.0f;

        for (int term = 0; term < 3; ++term) {
            const uint32_t ta = (term == 2) ? 1u : 0u;
            const uint32_t tb = (term == 1) ? 1u : 0u;
            const uint32_t wbase = sbase + P3_W + ta * 32768;
            const uint32_t xbase = sbase + P3_H + tb * 16384;
#pragma unroll
            for (int kt = 0; kt < 8; ++kt) {
                const uint32_t half = kt >> 2;
                const uint32_t klo2 = (kt & 3) * 32;
                const uint32_t wb = wbase + half * 16384;
                const uint32_t xb = xbase + half * 8192;
                uint32_t a0[4], a1[4], bfr[8][2];
                ldsm_x4(a0, wb + a_rb0 + ((klo2 + a_k16) ^ a_xor));
                ldsm_x4(a1, wb + a_rb1 + ((klo2 + a_k16) ^ a_xor));
#pragma unroll
                for (int nt = 0; nt < 8; ++nt)
                    ldsm_x2(bfr[nt], xb + b_rb + nt * 1024 + ((klo2 + b_k16) ^ b_xor));
#pragma unroll
                for (int nt = 0; nt < 8; ++nt) {
                    mma_bf16(acc[0][nt], a0, bfr[nt]);
                    mma_bf16(acc[1][nt], a1, bfr[nt]);
                }
            }
        }

        // fragments -> shf as out[t][d]
        const int dr = lane >> 2, dc = (lane & 3) * 2;
#pragma unroll
        for (int mt = 0; mt < 2; ++mt) {
            const int d = d0 + mt * 16 + dr;
#pragma unroll
            for (int nt = 0; nt < 8; ++nt) {
                const int t0 = nt * 8 + dc;
                shf[t0 * P3S + d]           = acc[mt][nt][0];
                shf[(t0 + 1) * P3S + d]     = acc[mt][nt][1];
                shf[t0 * P3S + d + 8]       = acc[mt][nt][2];
                shf[(t0 + 1) * P3S + d + 8] = acc[mt][nt][3];
            }
        }
    }
    __syncthreads();

    // Epilogue: out = staged + y[t]*x[t,0], coalesced float4
    {
        float4* og = (float4*)(out + gbase);
#pragma unroll
        for (int j = 0; j < 16; ++j) {
            int i4 = tid + 128 * j;          // 2048 float4
            int t = i4 >> 5, d4 = i4 & 31;
            float4 v = *(const float4*)&shf[t * P3S + d4 * 4];
            float yv = sy[t] * sx0[t];
            v.x += yv; v.y += yv; v.z += yv; v.w += yv;
            og[i4] = v;
        }
    }
}

// ---------------------------------------------------------------------------
extern "C" void kernel_launch(void* const* d_in, const int* in_sizes, int n_in,
                              void* d_out, int out_size)
{
    const float* x     = (const float*)d_in[0];
    const float* log_A = (const float*)d_in[1];
    const float* W_B   = (const float*)d_in[2];
    const float* W_C   = (const float*)d_in[3];
    const float* W_dt  = (const float*)d_in[4];
    const float* b_dt  = (const float*)d_in[5];
    const float* W_out = (const float*)d_in[6];
    float* out = (float*)d_out;

    cudaFuncSetAttribute(pass1_mma, cudaFuncAttributeMaxDynamicSharedMemorySize, SMEM1_BYTES);
    cudaFuncSetAttribute(pass2_kernel, cudaFuncAttributeMaxDynamicSharedMemorySize, SMEM2_BYTES);
    cudaFuncSetAttribute(pass3_mma, cudaFuncAttributeMaxDynamicSharedMemorySize, SMEM3_BYTES);

    prep_kernel<<<256, 256>>>(W_B, W_C, W_dt, W_out);
    pass1_mma<<<dim3(NC, NB), 128, SMEM1_BYTES>>>(x, log_A, b_dt);
    pass2_kernel<<<NB, 128, SMEM2_BYTES>>>();
    pass3_mma<<<dim3(NC, NB), 128, SMEM3_BYTES>>>(x, out);
}

// round 8
// speedup vs baseline: 2.6371x; 1.0857x over previous
#include <cuda_runtime.h>
#include <cuda_bf16.h>
#include <cstdint>
#include <cstddef>

#define NB 8
#define NT 8192
#define ND 128
#define NS 128
#define CK 64
#define NC (NT / CK)   // 128

// Scratch (allocation-free rule: __device__ globals)
__device__ float g_hl[(size_t)NB * NT * NS];
__device__ float g_p [(size_t)NB * NT * NS];
__device__ float g_C [(size_t)NB * NT * NS];
__device__ float g_h0[(size_t)NB * NC * NS];
// Pre-swizzled bf16 hi/lo tiles: [mat(dt,B,C,out)][term(hi,lo)][khalf] 128r x 64k (16KB)
__device__ __align__(16) unsigned char g_Wb[4 * 2 * 2 * 16384];

__device__ __forceinline__ uint32_t smem_u32(const void* p) {
    uint32_t a;
    asm("{ .reg .u64 t; cvta.to.shared.u64 t, %1; cvt.u32.u64 %0, t; }" : "=r"(a) : "l"(p));
    return a;
}
__device__ __forceinline__ uint32_t sw128(uint32_t off) { return off ^ ((off >> 3) & 0x70); }

__device__ __forceinline__ void ldsm_x4(uint32_t* r, uint32_t addr) {
    asm volatile("ldmatrix.sync.aligned.m8n8.x4.shared.b16 {%0,%1,%2,%3}, [%4];"
        : "=r"(r[0]), "=r"(r[1]), "=r"(r[2]), "=r"(r[3]) : "r"(addr));
}
__device__ __forceinline__ void ldsm_x2(uint32_t* r, uint32_t addr) {
    asm volatile("ldmatrix.sync.aligned.m8n8.x2.shared.b16 {%0,%1}, [%2];"
        : "=r"(r[0]), "=r"(r[1]) : "r"(addr));
}
__device__ __forceinline__ void mma_bf16(float* d, const uint32_t* a, const uint32_t* b) {
    asm volatile("mma.sync.aligned.m16n8k16.row.col.f32.bf16.bf16.f32 "
        "{%0,%1,%2,%3}, {%4,%5,%6,%7}, {%8,%9}, {%0,%1,%2,%3};"
        : "+f"(d[0]), "+f"(d[1]), "+f"(d[2]), "+f"(d[3])
        : "r"(a[0]), "r"(a[1]), "r"(a[2]), "r"(a[3]), "r"(b[0]), "r"(b[1]));
}

// ---------------------------------------------------------------------------
// Prep: convert 4 weight mats to swizzled bf16 hi/lo k-half tiles in global.
// ---------------------------------------------------------------------------
__global__ void prep_kernel(const float* __restrict__ W_B,
                            const float* __restrict__ W_C,
                            const float* __restrict__ W_dt,
                            const float* __restrict__ W_out)
{
    int e = blockIdx.x * 256 + threadIdx.x;
    if (e >= 4 * 16384) return;
    int mat = e >> 14, rk = e & 16383, r = rk >> 7, k = rk & 127;
    const float* W = (mat == 0) ? W_dt : (mat == 1) ? W_B : (mat == 2) ? W_C : W_out;
    float w = W[rk];
    __nv_bfloat16 hi = __float2bfloat16(w);
    __nv_bfloat16 lo = __float2bfloat16(w - __bfloat162float(hi));
    int half = k >> 6, kl = k & 63;
    uint32_t off = sw128((uint32_t)(r * 128 + kl * 2));
    *(__nv_bfloat16*)&g_Wb[((mat * 2 + 0) * 2 + half) * 16384 + off] = hi;
    *(__nv_bfloat16*)&g_Wb[((mat * 2 + 1) * 2 + half) * 16384 + off] = lo;
}

// ---------------------------------------------------------------------------
// Pass 1 (HMMA, 256 thr): X chunk -> bf16 hi/lo tiles; per mat (dt,B,C):
// stage W, mma m16n8k16 (1 m-tile/warp x 8n x 8k x 3 terms), dump D to smem.
// Tail: threads 0-127 scan + store p/hl; threads 128-255 stream C coalesced.
// ---------------------------------------------------------------------------
#define SM_X   0
#define SM_W   32768
#define SM_D   98304
#define SDS    66
#define SMEM1_BYTES (98304 + 3 * 128 * SDS * 4)

__global__ __launch_bounds__(256)
void pass1_mma(const float* __restrict__ x,
               const float* __restrict__ log_A,
               const float* __restrict__ b_dt)
{
    extern __shared__ unsigned char smraw[];
    const uint32_t sbase = smem_u32(smraw);
    float* sD = (float*)(smraw + SM_D);
    const int c = blockIdx.x, b = blockIdx.y, tid = threadIdx.x;
    const int wid = tid >> 5, lane = tid & 31;

    // Phase A: convert X chunk (64 tok x 128) to bf16 hi/lo swizzled tiles
    {
        const float4* xg = (const float4*)(x + ((size_t)b * NT + (size_t)c * CK) * ND);
        unsigned char* sX = smraw + SM_X;
#pragma unroll
        for (int j = 0; j < 8; ++j) {
            int idx = tid + 256 * j;                 // 2048 float4
            float4 v = xg[idx];
            int token = idx >> 5, k4 = idx & 31;
            int half = k4 >> 4;
            uint32_t off = (uint32_t)(token * 128) +
                           (((uint32_t)(k4 & 15) * 8) ^ ((uint32_t)(token & 7) << 4));
            __nv_bfloat162 h01 = __float22bfloat162_rn(make_float2(v.x, v.y));
            __nv_bfloat162 h23 = __float22bfloat162_rn(make_float2(v.z, v.w));
            __nv_bfloat162 l01 = __float22bfloat162_rn(make_float2(
                v.x - __bfloat162float(h01.x), v.y - __bfloat162float(h01.y)));
            __nv_bfloat162 l23 = __float22bfloat162_rn(make_float2(
                v.z - __bfloat162float(h23.x), v.w - __bfloat162float(h23.y)));
            *(__nv_bfloat162*)(sX + half * 8192 + off)             = h01;
            *(__nv_bfloat162*)(sX + half * 8192 + off + 4)         = h23;
            *(__nv_bfloat162*)(sX + 16384 + half * 8192 + off)     = l01;
            *(__nv_bfloat162*)(sX + 16384 + half * 8192 + off + 4) = l23;
        }
    }

    // Per-lane ldmatrix address components (one m16 tile per warp: rows wid*16..+15)
    const int s0 = wid * 16;
    const uint32_t aj = lane >> 3, ar = lane & 7;
    const uint32_t arow = (aj & 1) * 8 + ar;
    const uint32_t a_k16 = (aj >> 1) * 16;
    const uint32_t a_xor = ar << 4;
    const uint32_t a_rb  = (s0 + arow) * 128;
    const uint32_t bj = (lane >> 3) & 1, br = lane & 7;
    const uint32_t b_k16 = bj * 16;
    const uint32_t b_xor = br << 4;
    const uint32_t b_rb  = br * 128;

    for (int mat = 0; mat < 3; ++mat) {
        __syncthreads();
        {
            const float4* src = (const float4*)(g_Wb + (size_t)mat * 65536);
            float4* dst = (float4*)(smraw + SM_W);
#pragma unroll
            for (int j = 0; j < 16; ++j) dst[tid + 256 * j] = src[tid + 256 * j];
        }
        __syncthreads();

        float acc[8][4];
#pragma unroll
        for (int nt = 0; nt < 8; ++nt)
#pragma unroll
            for (int q = 0; q < 4; ++q) acc[nt][q] = 0.0f;

        for (int term = 0; term < 3; ++term) {
            const uint32_t ta = (term == 2) ? 1u : 0u;
            const uint32_t tb = (term == 1) ? 1u : 0u;
            const uint32_t wbase = sbase + SM_W + ta * 32768;
            const uint32_t xbase = sbase + SM_X + tb * 16384;
#pragma unroll
            for (int kt = 0; kt < 8; ++kt) {
                const uint32_t half = kt >> 2;
                const uint32_t klo2 = (kt & 3) * 32;
                const uint32_t wb = wbase + half * 16384;
                const uint32_t xb = xbase + half * 8192;
                uint32_t a0[4], bfr[8][2];
                ldsm_x4(a0, wb + a_rb + ((klo2 + a_k16) ^ a_xor));
#pragma unroll
                for (int nt = 0; nt < 8; ++nt)
                    ldsm_x2(bfr[nt], xb + b_rb + nt * 1024 + ((klo2 + b_k16) ^ b_xor));
#pragma unroll
                for (int nt = 0; nt < 8; ++nt) mma_bf16(acc[nt], a0, bfr[nt]);
            }
        }

        float* dm = sD + mat * (128 * SDS);
        const int dr = lane >> 2, dc = (lane & 3) * 2;
        const int sw = s0 + dr;
#pragma unroll
        for (int nt = 0; nt < 8; ++nt) {
            const int t0 = nt * 8 + dc;
            *(float2*)&dm[sw * SDS + t0]       = make_float2(acc[nt][0], acc[nt][1]);
            *(float2*)&dm[(sw + 8) * SDS + t0] = make_float2(acc[nt][2], acc[nt][3]);
        }
    }
    __syncthreads();

    // Tail: scan (tid<128) + coalesced C streaming (tid>=128)
    if (tid < 128) {
        const int s = tid;
        const float A_s = -fminf(__expf(log_A[s]), 10.0f);
        const float bd  = b_dt[s];
        float cs = 0.0f, acc = 0.0f;
        const size_t gb = ((size_t)b * NT + (size_t)c * CK) * NS + s;
        const float* rdt = sD + 0 * (128 * SDS) + s * SDS;
        const float* rbx = sD + 1 * (128 * SDS) + s * SDS;
#pragma unroll 4
        for (int t = 0; t < 64; ++t) {
            float v  = rdt[t] + bd;
            float sp = (v > 15.0f) ? v : __logf(1.0f + __expf(v));
            float dt = fminf(sp, 1.0f);
            float la = fminf(fmaxf(dt * A_s, -0.5f), 0.0f);
            float u  = rbx[t] * dt;
            cs += la;
            float lp = fminf(fmaxf(cs, -30.0f), 0.0f);
            float p  = __expf(lp);
            acc = fmaf(u, __expf(-lp), acc);
            const size_t gi = gb + (size_t)t * NS;
            g_p[gi]  = p;
            g_hl[gi] = p * acc;
        }
    } else {
        const int s = tid - 128;
        const size_t gb = ((size_t)b * NT + (size_t)c * CK) * NS + s;
        const float* rc = sD + 2 * (128 * SDS) + s * SDS;
#pragma unroll 8
        for (int t = 0; t < 64; ++t) g_C[gb + (size_t)t * NS] = rc[t];
    }
}

// ---------------------------------------------------------------------------
// Pass 2: inter-chunk prefix scan (unchanged)
// ---------------------------------------------------------------------------
#define SMEM2_BYTES (2 * 128 * 128 * 4)

__global__ __launch_bounds__(128)
void pass2_kernel()
{
    extern __shared__ float smf[];
    float* sP = smf;
    float* sH = smf + 128 * 128;
    const int b = blockIdx.x, tid = threadIdx.x;

    const size_t bb = (size_t)b * NT * NS;
    for (int i = tid; i < 128 * 128; i += 128) {
        int c = i >> 7, s = i & 127;
        size_t gi = bb + (size_t)(c * CK + (CK - 1)) * NS + s;
        sP[i] = g_p[gi];
        sH[i] = g_hl[gi];
    }
    __syncthreads();

    const int s = tid;
    float h0 = 0.0f;
    const size_t hb = (size_t)b * NC * NS + s;
#pragma unroll 8
    for (int c = 0; c < NC; ++c) {
        g_h0[hb + (size_t)c * NS] = h0;
        h0 = fmaf(sP[c * 128 + s], h0, sH[c * 128 + s]);
    }
}

// ---------------------------------------------------------------------------
// Pass 3 (HMMA, 256 thr): h = hl + p*h0 (fp32 + bf16 hi/lo); y = C.h (fp32);
// out[d][t] = W_out h^T via mma (1 m-tile/warp); epilogue adds y[t]*x[t,0].
// ---------------------------------------------------------------------------
#define P3_W 0
#define P3_H 65536
#define P3_F 98304
#define P3S  132
#define P3_Y (98304 + 64 * P3S * 4)
#define SMEM3_BYTES (P3_Y + (64 + 128 + 64) * 4)

__global__ __launch_bounds__(256)
void pass3_mma(const float* __restrict__ x,
               float* __restrict__ out)
{
    extern __shared__ unsigned char smraw[];
    const uint32_t sbase = smem_u32(smraw);
    float* shf = (float*)(smraw + P3_F);    // fp32 h, later reused as out stage
    float* sy  = (float*)(smraw + P3_Y);
    float* sh0 = sy + 64;
    float* sx0 = sh0 + 128;
    const int c = blockIdx.x, b = blockIdx.y, tid = threadIdx.x;
    const int wid = tid >> 5, lane = tid & 31;
    const size_t tbase = (size_t)b * NT + (size_t)c * CK;
    const size_t gbase = tbase * NS;

    // Stage W_out hi/lo tiles (64KB)
    {
        const float4* src = (const float4*)(g_Wb + (size_t)3 * 65536);
        float4* dst = (float4*)(smraw + P3_W);
#pragma unroll
        for (int j = 0; j < 16; ++j) dst[tid + 256 * j] = src[tid + 256 * j];
    }
    if (tid < 128) sh0[tid] = g_h0[((size_t)b * NC + c) * NS + tid];
    else if (tid < 192) sx0[tid - 128] = x[(tbase + tid - 128) * ND];
    __syncthreads();

    // Reconstruct h: fp32 into shf, bf16 hi/lo into swizzled tiles
    {
        unsigned char* sH = smraw + P3_H;
#pragma unroll
        for (int j = 0; j < 16; ++j) {
            int idx = tid + 256 * j;        // 4096 pairs
            int t = idx >> 6, sp = idx & 63;
            float2 pv = *(const float2*)&g_p [gbase + (size_t)t * NS + sp * 2];
            float2 hv = *(const float2*)&g_hl[gbase + (size_t)t * NS + sp * 2];
            float2 h;
            h.x = fmaf(pv.x, sh0[sp * 2],     hv.x);
            h.y = fmaf(pv.y, sh0[sp * 2 + 1], hv.y);
            *(float2*)&shf[t * P3S + sp * 2] = h;
            __nv_bfloat162 hi2 = __float22bfloat162_rn(h);
            __nv_bfloat162 lo2 = __float22bfloat162_rn(make_float2(
                h.x - __bfloat162float(hi2.x), h.y - __bfloat162float(hi2.y)));
            int half = sp >> 5, klp = sp & 31;
            uint32_t off = (uint32_t)(t * 128) + (((uint32_t)klp * 4) ^ ((uint32_t)(t & 7) << 4));
            *(__nv_bfloat162*)(sH + half * 8192 + off)         = hi2;
            *(__nv_bfloat162*)(sH + 16384 + half * 8192 + off) = lo2;
        }
    }
    __syncthreads();

    // y[t] = sum_s C[t][s]*h[t][s]  (8 warps x 8 tokens, exact fp32)
    {
        const float4* C4 = (const float4*)(g_C + gbase);
        for (int t = wid * 8; t < wid * 8 + 8; ++t) {
            float4 cv = C4[t * 32 + lane];
            const float* hr = &shf[t * P3S + lane * 4];
            float v = cv.x * hr[0] + cv.y * hr[1] + cv.z * hr[2] + cv.w * hr[3];
#pragma unroll
            for (int o = 16; o; o >>= 1) v += __shfl_xor_sync(0xFFFFFFFFu, v, o);
            if (lane == 0) sy[t] = v;
        }
    }
    __syncthreads();   // y done; shf region free for out staging

    // MMA: D[d][t] = W_out h^T (3-term bf16), one m16 tile per warp
    {
        const int d0 = wid * 16;
        const uint32_t aj = lane >> 3, ar = lane & 7;
        const uint32_t arow = (aj & 1) * 8 + ar;
        const uint32_t a_k16 = (aj >> 1) * 16;
        const uint32_t a_xor = ar << 4;
        const uint32_t a_rb  = (d0 + arow) * 128;
        const uint32_t bj = (lane >> 3) & 1, br = lane & 7;
        const uint32_t b_k16 = bj * 16;
        const uint32_t b_xor = br << 4;
        const uint32_t b_rb  = br * 128;

        float acc[8][4];
#pragma unroll
        for (int nt = 0; nt < 8; ++nt)
#pragma unroll
            for (int q = 0; q < 4; ++q) acc[nt][q] = 0.0f;

        for (int term = 0; term < 3; ++term) {
            const uint32_t ta = (term == 2) ? 1u : 0u;
            const uint32_t tb = (term == 1) ? 1u : 0u;
            const uint32_t wbase = sbase + P3_W + ta * 32768;
            const uint32_t xbase = sbase + P3_H + tb * 16384;
#pragma unroll
            for (int kt = 0; kt < 8; ++kt) {
                const uint32_t half = kt >> 2;
                const uint32_t klo2 = (kt & 3) * 32;
                const uint32_t wb = wbase + half * 16384;
                const uint32_t xb = xbase + half * 8192;
                uint32_t a0[4], bfr[8][2];
                ldsm_x4(a0, wb + a_rb + ((klo2 + a_k16) ^ a_xor));
#pragma unroll
                for (int nt = 0; nt < 8; ++nt)
                    ldsm_x2(bfr[nt], xb + b_rb + nt * 1024 + ((klo2 + b_k16) ^ b_xor));
#pragma unroll
                for (int nt = 0; nt < 8; ++nt) mma_bf16(acc[nt], a0, bfr[nt]);
            }
        }

        // fragments -> shf as out[t][d]
        const int dr = lane >> 2, dc = (lane & 3) * 2;
        const int d = d0 + dr;
#pragma unroll
        for (int nt = 0; nt < 8; ++nt) {
            const int t0 = nt * 8 + dc;
            shf[t0 * P3S + d]           = acc[nt][0];
            shf[(t0 + 1) * P3S + d]     = acc[nt][1];
            shf[t0 * P3S + d + 8]       = acc[nt][2];
            shf[(t0 + 1) * P3S + d + 8] = acc[nt][3];
        }
    }
    __syncthreads();

    // Epilogue: out = staged + y[t]*x[t,0], coalesced float4
    {
        float4* og = (float4*)(out + gbase);
#pragma unroll
        for (int j = 0; j < 8; ++j) {
            int i4 = tid + 256 * j;          // 2048 float4
            int t = i4 >> 5, d4 = i4 & 31;
            float4 v = *(const float4*)&shf[t * P3S + d4 * 4];
            float yv = sy[t] * sx0[t];
            v.x += yv; v.y += yv; v.z += yv; v.w += yv;
            og[i4] = v;
        }
    }
}

// ---------------------------------------------------------------------------
extern "C" void kernel_launch(void* const* d_in, const int* in_sizes, int n_in,
                              void* d_out, int out_size)
{
    const float* x     = (const float*)d_in[0];
    const float* log_A = (const float*)d_in[1];
    const float* W_B   = (const float*)d_in[2];
    const float* W_C   = (const float*)d_in[3];
    const float* W_dt  = (const float*)d_in[4];
    const float* b_dt  = (const float*)d_in[5];
    const float* W_out = (const float*)d_in[6];
    float* out = (float*)d_out;

    cudaFuncSetAttribute(pass1_mma, cudaFuncAttributeMaxDynamicSharedMemorySize, SMEM1_BYTES);
    cudaFuncSetAttribute(pass2_kernel, cudaFuncAttributeMaxDynamicSharedMemorySize, SMEM2_BYTES);
    cudaFuncSetAttribute(pass3_mma, cudaFuncAttributeMaxDynamicSharedMemorySize, SMEM3_BYTES);

    prep_kernel<<<256, 256>>>(W_B, W_C, W_dt, W_out);
    pass1_mma<<<dim3(NC, NB), 256, SMEM1_BYTES>>>(x, log_A, b_dt);
    pass2_kernel<<<NB, 128, SMEM2_BYTES>>>();
    pass3_mma<<<dim3(NC, NB), 256, SMEM3_BYTES>>>(x, out);
}

// round 9
// speedup vs baseline: 3.1846x; 1.2076x over previous
#include <cuda_runtime.h>
#include <cuda_bf16.h>
#include <cstdint>
#include <cstddef>

#define NB 8
#define NT 8192
#define ND 128
#define NS 128
#define CK 64
#define NC (NT / CK)   // 128

// Scratch (allocation-free rule: __device__ globals)
__device__ float g_hl[(size_t)NB * NT * NS];
__device__ float g_p [(size_t)NB * NT * NS];
__device__ float g_C [(size_t)NB * NT * NS];
__device__ float g_h0[(size_t)NB * NC * NS];
// Pre-swizzled bf16 hi/lo tiles: [mat(dt,B,C,out)][term(hi,lo)][khalf] 128r x 64k (16KB)
__device__ __align__(16) unsigned char g_Wb[4 * 2 * 2 * 16384];

__device__ __forceinline__ uint32_t smem_u32(const void* p) {
    uint32_t a;
    asm("{ .reg .u64 t; cvta.to.shared.u64 t, %1; cvt.u32.u64 %0, t; }" : "=r"(a) : "l"(p));
    return a;
}
__device__ __forceinline__ uint32_t sw128(uint32_t off) { return off ^ ((off >> 3) & 0x70); }

__device__ __forceinline__ void cp_async16(uint32_t dst, const void* src) {
    asm volatile("cp.async.cg.shared.global [%0], [%1], 16;" :: "r"(dst), "l"(src));
}
#define CP_COMMIT() asm volatile("cp.async.commit_group;" ::: "memory")
#define CP_WAIT0()  asm volatile("cp.async.wait_group 0;" ::: "memory")

__device__ __forceinline__ void ldsm_x4(uint32_t* r, uint32_t addr) {
    asm volatile("ldmatrix.sync.aligned.m8n8.x4.shared.b16 {%0,%1,%2,%3}, [%4];"
        : "=r"(r[0]), "=r"(r[1]), "=r"(r[2]), "=r"(r[3]) : "r"(addr));
}
__device__ __forceinline__ void mma_bf16(float* d, const uint32_t* a, const uint32_t* b) {
    asm volatile("mma.sync.aligned.m16n8k16.row.col.f32.bf16.bf16.f32 "
        "{%0,%1,%2,%3}, {%4,%5,%6,%7}, {%8,%9}, {%0,%1,%2,%3};"
        : "+f"(d[0]), "+f"(d[1]), "+f"(d[2]), "+f"(d[3])
        : "r"(a[0]), "r"(a[1]), "r"(a[2]), "r"(a[3]), "r"(b[0]), "r"(b[1]));
}

// ---------------------------------------------------------------------------
// Prep: convert 4 weight mats to swizzled bf16 hi/lo k-half tiles in global.
// ---------------------------------------------------------------------------
__global__ void prep_kernel(const float* __restrict__ W_B,
                            const float* __restrict__ W_C,
                            const float* __restrict__ W_dt,
                            const float* __restrict__ W_out)
{
    int e = blockIdx.x * 256 + threadIdx.x;
    if (e >= 4 * 16384) return;
    int mat = e >> 14, rk = e & 16383, r = rk >> 7, k = rk & 127;
    const float* W = (mat == 0) ? W_dt : (mat == 1) ? W_B : (mat == 2) ? W_C : W_out;
    float w = W[rk];
    __nv_bfloat16 hi = __float2bfloat16(w);
    __nv_bfloat16 lo = __float2bfloat16(w - __bfloat162float(hi));
    int half = k >> 6, kl = k & 63;
    uint32_t off = sw128((uint32_t)(r * 128 + kl * 2));
    *(__nv_bfloat16*)&g_Wb[((mat * 2 + 0) * 2 + half) * 16384 + off] = hi;
    *(__nv_bfloat16*)&g_Wb[((mat * 2 + 1) * 2 + half) * 16384 + off] = lo;
}

// ---------------------------------------------------------------------------
// Pass 1 (HMMA, 256 thr, 2 MMA stages):
//  smem: X/C 32KB | W 3x32KB (one term per stage) | D(dt,Bx) 2x64x132x4
//  Stage1 (W_hi via cp.async overlapped with X convert): terms (hi,hi),(hi,lo)
//  Stage2 (W_lo restage): term (lo,hi). B fragments shared across 3 mats.
//  Tail: threads 0-127 scan; 128-255 stream C coalesced.
// ---------------------------------------------------------------------------
#define SM_X   0
#define SM_W   32768
#define SM_D   131072
#define DST    132
#define SMEM1_BYTES (131072 + 2 * 64 * DST * 4)   // 198656

__global__ __launch_bounds__(256)
void pass1_mma(const float* __restrict__ x,
               const float* __restrict__ log_A,
               const float* __restrict__ b_dt)
{
    extern __shared__ unsigned char smraw[];
    const uint32_t sbase = smem_u32(smraw);
    const int c = blockIdx.x, b = blockIdx.y, tid = threadIdx.x;
    const int wid = tid >> 5, lane = tid & 31;

    // Issue cp.async for W_hi (3 mats x 32KB) -- overlaps with X convert below
    {
#pragma unroll
        for (int j = 0; j < 24; ++j) {
            int idx = tid + 256 * j;               // 6144 16B chunks
            int mat = idx >> 11, rem = idx & 2047;
            cp_async16(sbase + SM_W + (uint32_t)idx * 16,
                       g_Wb + (size_t)mat * 65536 + (size_t)rem * 16);
        }
        CP_COMMIT();
    }

    // Convert X chunk (64 tok x 128) to bf16 hi/lo swizzled tiles
    {
        const float4* xg = (const float4*)(x + ((size_t)b * NT + (size_t)c * CK) * ND);
        unsigned char* sX = smraw + SM_X;
#pragma unroll
        for (int j = 0; j < 8; ++j) {
            int idx = tid + 256 * j;                 // 2048 float4
            float4 v = xg[idx];
            int token = idx >> 5, k4 = idx & 31;
            int half = k4 >> 4;
            uint32_t off = (uint32_t)(token * 128) +
                           (((uint32_t)(k4 & 15) * 8) ^ ((uint32_t)(token & 7) << 4));
            __nv_bfloat162 h01 = __float22bfloat162_rn(make_float2(v.x, v.y));
            __nv_bfloat162 h23 = __float22bfloat162_rn(make_float2(v.z, v.w));
            __nv_bfloat162 l01 = __float22bfloat162_rn(make_float2(
                v.x - __bfloat162float(h01.x), v.y - __bfloat162float(h01.y)));
            __nv_bfloat162 l23 = __float22bfloat162_rn(make_float2(
                v.z - __bfloat162float(h23.x), v.w - __bfloat162float(h23.y)));
            *(__nv_bfloat162*)(sX + half * 8192 + off)             = h01;
            *(__nv_bfloat162*)(sX + half * 8192 + off + 4)         = h23;
            *(__nv_bfloat162*)(sX + 16384 + half * 8192 + off)     = l01;
            *(__nv_bfloat162*)(sX + 16384 + half * 8192 + off + 4) = l23;
        }
    }
    CP_WAIT0();
    __syncthreads();

    // Per-lane ldmatrix address components
    const int s0 = wid * 16;
    const uint32_t ar = lane & 7, aj = lane >> 3;
    const uint32_t a_rb  = (uint32_t)(s0 + (aj & 1) * 8 + ar) * 128;
    const uint32_t a_k16 = (aj >> 1) * 16;
    const uint32_t a_xor = ar << 4;
    const uint32_t b_row = lane & 7, b_j = lane >> 3;
    const uint32_t b_off = (b_j >> 1) * 1024 + b_row * 128;
    const uint32_t b_k16 = (b_j & 1) * 16;
    const uint32_t b_xor = b_row << 4;

    float acc[3][8][4];
#pragma unroll
    for (int m = 0; m < 3; ++m)
#pragma unroll
        for (int nt = 0; nt < 8; ++nt)
#pragma unroll
            for (int q = 0; q < 4; ++q) acc[m][nt][q] = 0.0f;

    auto run_terms = [&](int tb0, int ntb) {
        for (int tb = tb0; tb < tb0 + ntb; ++tb) {
#pragma unroll
            for (int kt = 0; kt < 8; ++kt) {
                const uint32_t half = kt >> 2;
                const uint32_t klo2 = (kt & 3) * 32;
                const uint32_t xb = sbase + SM_X + (uint32_t)tb * 16384 + half * 8192;
                uint32_t bfr[4][4];
#pragma unroll
                for (int i = 0; i < 4; ++i)
                    ldsm_x4(bfr[i], xb + i * 2048 + b_off + ((klo2 + b_k16) ^ b_xor));
#pragma unroll
                for (int mat = 0; mat < 3; ++mat) {
                    const uint32_t wb = sbase + SM_W + (uint32_t)mat * 32768 + half * 16384;
                    uint32_t a0[4];
                    ldsm_x4(a0, wb + a_rb + ((klo2 + a_k16) ^ a_xor));
#pragma unroll
                    for (int i = 0; i < 4; ++i) {
                        mma_bf16(acc[mat][2 * i],     a0, &bfr[i][0]);
                        mma_bf16(acc[mat][2 * i + 1], a0, &bfr[i][2]);
                    }
                }
            }
        }
    };

    run_terms(0, 2);            // W_hi x (X_hi, X_lo)
    __syncthreads();
    {                            // restage W_lo
#pragma unroll
        for (int j = 0; j < 24; ++j) {
            int idx = tid + 256 * j;
            int mat = idx >> 11, rem = idx & 2047;
            cp_async16(sbase + SM_W + (uint32_t)idx * 16,
                       g_Wb + (size_t)mat * 65536 + 32768 + (size_t)rem * 16);
        }
        CP_COMMIT();
        CP_WAIT0();
    }
    __syncthreads();
    run_terms(0, 1);            // W_lo x X_hi
    __syncthreads();            // all X reads done -> X region reusable for C

    // Fragment writes: dt,Bx -> D [t][s] stride 132; C -> X region [t][s] stride 128
    {
        const int dr = lane >> 2, dc = (lane & 3) * 2;
        const int sw = s0 + dr;
        float* dD = (float*)(smraw + SM_D);
        float* dC = (float*)(smraw + SM_X);
#pragma unroll
        for (int mat = 0; mat < 2; ++mat) {
            float* dm = dD + mat * (64 * DST);
#pragma unroll
            for (int nt = 0; nt < 8; ++nt) {
                const int t0 = nt * 8 + dc;
                dm[t0 * DST + sw]           = acc[mat][nt][0];
                dm[(t0 + 1) * DST + sw]     = acc[mat][nt][1];
                dm[t0 * DST + sw + 8]       = acc[mat][nt][2];
                dm[(t0 + 1) * DST + sw + 8] = acc[mat][nt][3];
            }
        }
#pragma unroll
        for (int nt = 0; nt < 8; ++nt) {
            const int t0 = nt * 8 + dc;
            dC[t0 * 128 + sw]           = acc[2][nt][0];
            dC[(t0 + 1) * 128 + sw]     = acc[2][nt][1];
            dC[t0 * 128 + sw + 8]       = acc[2][nt][2];
            dC[(t0 + 1) * 128 + sw + 8] = acc[2][nt][3];
        }
    }
    __syncthreads();

    // Tail: scan (tid<128) + coalesced C streaming (tid>=128)
    if (tid < 128) {
        const int s = tid;
        const float A_s = -fminf(__expf(log_A[s]), 10.0f);
        const float bd  = b_dt[s];
        float cs = 0.0f, acc2 = 0.0f;
        const size_t gb = ((size_t)b * NT + (size_t)c * CK) * NS + s;
        const float* rdt = (const float*)(smraw + SM_D) + s;
        const float* rbx = rdt + 64 * DST;
#pragma unroll 4
        for (int t = 0; t < 64; ++t) {
            float v  = rdt[t * DST] + bd;
            float sp = (v > 15.0f) ? v : __logf(1.0f + __expf(v));
            float dt = fminf(sp, 1.0f);
            float la = fminf(fmaxf(dt * A_s, -0.5f), 0.0f);
            float u  = rbx[t * DST] * dt;
            cs += la;
            float lp = fminf(fmaxf(cs, -30.0f), 0.0f);
            float p  = __expf(lp);
            acc2 = fmaf(u, __expf(-lp), acc2);
            const size_t gi = gb + (size_t)t * NS;
            g_p[gi]  = p;
            g_hl[gi] = p * acc2;
        }
    } else {
        const int s = tid - 128;
        const size_t gb = ((size_t)b * NT + (size_t)c * CK) * NS + s;
        const float* rc = (const float*)(smraw + SM_X) + s;
#pragma unroll 8
        for (int t = 0; t < 64; ++t) g_C[gb + (size_t)t * NS] = rc[t * 128];
    }
}

// ---------------------------------------------------------------------------
// Pass 2: inter-chunk prefix scan (unchanged)
// ---------------------------------------------------------------------------
#define SMEM2_BYTES (2 * 128 * 128 * 4)

__global__ __launch_bounds__(128)
void pass2_kernel()
{
    extern __shared__ float smf[];
    float* sP = smf;
    float* sH = smf + 128 * 128;
    const int b = blockIdx.x, tid = threadIdx.x;

    const size_t bb = (size_t)b * NT * NS;
    for (int i = tid; i < 128 * 128; i += 128) {
        int c = i >> 7, s = i & 127;
        size_t gi = bb + (size_t)(c * CK + (CK - 1)) * NS + s;
        sP[i] = g_p[gi];
        sH[i] = g_hl[gi];
    }
    __syncthreads();

    const int s = tid;
    float h0 = 0.0f;
    const size_t hb = (size_t)b * NC * NS + s;
#pragma unroll 8
    for (int c = 0; c < NC; ++c) {
        g_h0[hb + (size_t)c * NS] = h0;
        h0 = fmaf(sP[c * 128 + s], h0, sH[c * 128 + s]);
    }
}

// ---------------------------------------------------------------------------
// Pass 3 (HMMA, 256 thr, 2 CTAs/SM): W one term at a time (32KB).
// h = hl + p*h0 (fp32 + bf16 hi/lo); y = C.h (fp32); out = W_out h^T + y*x0.
// smem: W 32KB | H 32KB | shf 64x132x4 | y/h0/x0  = ~98KB
// ---------------------------------------------------------------------------
#define P3_W 0
#define P3_H 32768
#define P3_F 65536
#define P3S  132
#define P3_Y (65536 + 64 * P3S * 4)
#define SMEM3_BYTES (P3_Y + (64 + 128 + 64) * 4)   // 100352

__global__ __launch_bounds__(256, 2)
void pass3_mma(const float* __restrict__ x,
               float* __restrict__ out)
{
    extern __shared__ unsigned char smraw[];
    const uint32_t sbase = smem_u32(smraw);
    float* shf = (float*)(smraw + P3_F);
    float* sy  = (float*)(smraw + P3_Y);
    float* sh0 = sy + 64;
    float* sx0 = sh0 + 128;
    const int c = blockIdx.x, b = blockIdx.y, tid = threadIdx.x;
    const int wid = tid >> 5, lane = tid & 31;
    const size_t tbase = (size_t)b * NT + (size_t)c * CK;
    const size_t gbase = tbase * NS;

    // cp.async stage W_out_hi (32KB)
    {
#pragma unroll
        for (int j = 0; j < 8; ++j) {
            int idx = tid + 256 * j;   // 2048 chunks
            cp_async16(sbase + P3_W + (uint32_t)idx * 16,
                       g_Wb + (size_t)3 * 65536 + (size_t)idx * 16);
        }
        CP_COMMIT();
    }
    if (tid < 128) sh0[tid] = g_h0[((size_t)b * NC + c) * NS + tid];
    else if (tid < 192) sx0[tid - 128] = x[(tbase + tid - 128) * ND];
    __syncthreads();

    // Reconstruct h: fp32 into shf, bf16 hi/lo into swizzled tiles
    {
        unsigned char* sH = smraw + P3_H;
#pragma unroll
        for (int j = 0; j < 16; ++j) {
            int idx = tid + 256 * j;        // 4096 pairs
            int t = idx >> 6, sp = idx & 63;
            float2 pv = *(const float2*)&g_p [gbase + (size_t)t * NS + sp * 2];
            float2 hv = *(const float2*)&g_hl[gbase + (size_t)t * NS + sp * 2];
            float2 h;
            h.x = fmaf(pv.x, sh0[sp * 2],     hv.x);
            h.y = fmaf(pv.y, sh0[sp * 2 + 1], hv.y);
            *(float2*)&shf[t * P3S + sp * 2] = h;
            __nv_bfloat162 hi2 = __float22bfloat162_rn(h);
            __nv_bfloat162 lo2 = __float22bfloat162_rn(make_float2(
                h.x - __bfloat162float(hi2.x), h.y - __bfloat162float(hi2.y)));
            int half = sp >> 5, klp = sp & 31;
            uint32_t off = (uint32_t)(t * 128) + (((uint32_t)klp * 4) ^ ((uint32_t)(t & 7) << 4));
            *(__nv_bfloat162*)(sH + half * 8192 + off)         = hi2;
            *(__nv_bfloat162*)(sH + 16384 + half * 8192 + off) = lo2;
        }
    }
    __syncthreads();

    // y[t] = sum_s C[t][s]*h[t][s]  (8 warps x 8 tokens, exact fp32)
    {
        const float4* C4 = (const float4*)(g_C + gbase);
        for (int t = wid * 8; t < wid * 8 + 8; ++t) {
            float4 cv = C4[t * 32 + lane];
            const float* hr = &shf[t * P3S + lane * 4];
            float v = cv.x * hr[0] + cv.y * hr[1] + cv.z * hr[2] + cv.w * hr[3];
#pragma unroll
            for (int o = 16; o; o >>= 1) v += __shfl_xor_sync(0xFFFFFFFFu, v, o);
            if (lane == 0) sy[t] = v;
        }
    }
    CP_WAIT0();
    __syncthreads();   // y done; W_hi ready; shf free for out staging after this

    // MMA: D[d][t] = W_out h^T, one m16 tile per warp, B x4 loads
    const int d0 = wid * 16;
    const uint32_t ar = lane & 7, aj = lane >> 3;
    const uint32_t a_rb  = (uint32_t)(d0 + (aj & 1) * 8 + ar) * 128;
    const uint32_t a_k16 = (aj >> 1) * 16;
    const uint32_t a_xor = ar << 4;
    const uint32_t b_row = lane & 7, b_j = lane >> 3;
    const uint32_t b_off = (b_j >> 1) * 1024 + b_row * 128;
    const uint32_t b_k16 = (b_j & 1) * 16;
    const uint32_t b_xor = b_row << 4;

    float acc[8][4];
#pragma unroll
    for (int nt = 0; nt < 8; ++nt)
#pragma unroll
        for (int q = 0; q < 4; ++q) acc[nt][q] = 0.0f;

    auto run_terms3 = [&](int tb0, int ntb) {
        for (int tb = tb0; tb < tb0 + ntb; ++tb) {
#pragma unroll
            for (int kt = 0; kt < 8; ++kt) {
                const uint32_t half = kt >> 2;
                const uint32_t klo2 = (kt & 3) * 32;
                const uint32_t xb = sbase + P3_H + (uint32_t)tb * 16384 + half * 8192;
                const uint32_t wb = sbase + P3_W + half * 16384;
                uint32_t a0[4];
                ldsm_x4(a0, wb + a_rb + ((klo2 + a_k16) ^ a_xor));
#pragma unroll
                for (int i = 0; i < 4; ++i) {
                    uint32_t bfr[4];
                    ldsm_x4(bfr, xb + i * 2048 + b_off + ((klo2 + b_k16) ^ b_xor));
                    mma_bf16(acc[2 * i],     a0, &bfr[0]);
                    mma_bf16(acc[2 * i + 1], a0, &bfr[2]);
                }
            }
        }
    };

    run_terms3(0, 2);           // W_hi x (H_hi, H_lo)
    __syncthreads();
    {                            // restage W_lo
#pragma unroll
        for (int j = 0; j < 8; ++j) {
            int idx = tid + 256 * j;
            cp_async16(sbase + P3_W + (uint32_t)idx * 16,
                       g_Wb + (size_t)3 * 65536 + 32768 + (size_t)idx * 16);
        }
        CP_COMMIT();
        CP_WAIT0();
    }
    __syncthreads();
    run_terms3(0, 1);           // W_lo x H_hi
    __syncthreads();

    // fragments -> shf as out[t][d]
    {
        const int dr = lane >> 2, dc = (lane & 3) * 2;
        const int d = d0 + dr;
#pragma unroll
        for (int nt = 0; nt < 8; ++nt) {
            const int t0 = nt * 8 + dc;
            shf[t0 * P3S + d]           = acc[nt][0];
            shf[(t0 + 1) * P3S + d]     = acc[nt][1];
            shf[t0 * P3S + d + 8]       = acc[nt][2];
            shf[(t0 + 1) * P3S + d + 8] = acc[nt][3];
        }
    }
    __syncthreads();

    // Epilogue: out = staged + y[t]*x[t,0], coalesced float4
    {
        float4* og = (float4*)(out + gbase);
#pragma unroll
        for (int j = 0; j < 8; ++j) {
            int i4 = tid + 256 * j;          // 2048 float4
            int t = i4 >> 5, d4 = i4 & 31;
            float4 v = *(const float4*)&shf[t * P3S + d4 * 4];
            float yv = sy[t] * sx0[t];
            v.x += yv; v.y += yv; v.z += yv; v.w += yv;
            og[i4] = v;
        }
    }
}

// ---------------------------------------------------------------------------
extern "C" void kernel_launch(void* const* d_in, const int* in_sizes, int n_in,
                              void* d_out, int out_size)
{
    const float* x     = (const float*)d_in[0];
    const float* log_A = (const float*)d_in[1];
    const float* W_B   = (const float*)d_in[2];
    const float* W_C   = (const float*)d_in[3];
    const float* W_dt  = (const float*)d_in[4];
    const float* b_dt  = (const float*)d_in[5];
    const float* W_out = (const float*)d_in[6];
    float* out = (float*)d_out;

    cudaFuncSetAttribute(pass1_mma, cudaFuncAttributeMaxDynamicSharedMemorySize, SMEM1_BYTES);
    cudaFuncSetAttribute(pass2_kernel, cudaFuncAttributeMaxDynamicSharedMemorySize, SMEM2_BYTES);
    cudaFuncSetAttribute(pass3_mma, cudaFuncAttributeMaxDynamicSharedMemorySize, SMEM3_BYTES);

    prep_kernel<<<256, 256>>>(W_B, W_C, W_dt, W_out);
    pass1_mma<<<dim3(NC, NB), 256, SMEM1_BYTES>>>(x, log_A, b_dt);
    pass2_kernel<<<NB, 128, SMEM2_BYTES>>>();
    pass3_mma<<<dim3(NC, NB), 256, SMEM3_BYTES>>>(x, out);
}